// round 14
// baseline (speedup 1.0000x reference)
#include <cuda_runtime.h>
#include <cuda_fp16.h>
#include <math.h>

#define NN 50000
#define EE 800000
#define GG 1024
#define DD 64
#define DIN 9
#define NBLK ((NN + 255) / 256)    // 196

// ---- scratch ----
__device__ int   g_deg[NN];        // all-zero at entry; re-zeroed in k_fill each call
__device__ float g_dinv[NN];
__device__ int   g_rowptr[NN + 1];
__device__ int   g_cursor[NN];
__device__ int   g_csrsrc[EE];
__device__ unsigned long long g_blkDesc[NBLK];  // zeroed in k_hist each call
__device__ uint4 g_xs16[NN * 2];   // fp16 input features, 16 halves/node (9 used)
__device__ float g_hA[NN * DD];
__device__ float g_hB[NN * DD];

__device__ __forceinline__ float tanh_a(float x) {
    float y;
    asm("tanh.approx.f32 %0, %1;" : "=f"(y) : "f"(x));
    return y;
}
__device__ __forceinline__ unsigned int smem_u32(const void* p) {
    return (unsigned int)__cvta_generic_to_shared(p);
}
__device__ __forceinline__ void ldmx4(unsigned int& r0, unsigned int& r1,
                                      unsigned int& r2, unsigned int& r3, unsigned int a) {
    asm volatile("ldmatrix.sync.aligned.m8n8.x4.shared.b16 {%0,%1,%2,%3}, [%4];"
                 : "=r"(r0), "=r"(r1), "=r"(r2), "=r"(r3) : "r"(a));
}
__device__ __forceinline__ void ldmx4t(unsigned int& r0, unsigned int& r1,
                                       unsigned int& r2, unsigned int& r3, unsigned int a) {
    asm volatile("ldmatrix.sync.aligned.m8n8.x4.trans.shared.b16 {%0,%1,%2,%3}, [%4];"
                 : "=r"(r0), "=r"(r1), "=r"(r2), "=r"(r3) : "r"(a));
}
__device__ __forceinline__ void mma16816(float* c, unsigned int a0, unsigned int a1,
                                         unsigned int a2, unsigned int a3,
                                         unsigned int b0, unsigned int b1) {
    asm volatile("mma.sync.aligned.m16n8k16.row.col.f32.f16.f16.f32 "
                 "{%0,%1,%2,%3}, {%4,%5,%6,%7}, {%8,%9}, {%0,%1,%2,%3};"
                 : "+f"(c[0]), "+f"(c[1]), "+f"(c[2]), "+f"(c[3])
                 : "r"(a0), "r"(a1), "r"(a2), "r"(a3), "r"(b0), "r"(b1));
}

#define H2C(p) (*(const __half2*)&(p))

// ------------------- preprocessing -------------------

__global__ void k_hist(const int* __restrict__ col) {
    int i = blockIdx.x * blockDim.x + threadIdx.x;
    if (i < NBLK) g_blkDesc[i] = 0ULL;
    long long base = (long long)i * 16;
    if (base < EE) {
        const int4* c4 = reinterpret_cast<const int4*>(col) + i * 4;
        int4 a = c4[0], b = c4[1], c = c4[2], d = c4[3];
        atomicAdd(&g_deg[a.x], 1); atomicAdd(&g_deg[a.y], 1);
        atomicAdd(&g_deg[a.z], 1); atomicAdd(&g_deg[a.w], 1);
        atomicAdd(&g_deg[b.x], 1); atomicAdd(&g_deg[b.y], 1);
        atomicAdd(&g_deg[b.z], 1); atomicAdd(&g_deg[b.w], 1);
        atomicAdd(&g_deg[c.x], 1); atomicAdd(&g_deg[c.y], 1);
        atomicAdd(&g_deg[c.z], 1); atomicAdd(&g_deg[c.w], 1);
        atomicAdd(&g_deg[d.x], 1); atomicAdd(&g_deg[d.y], 1);
        atomicAdd(&g_deg[d.z], 1); atomicAdd(&g_deg[d.w], 1);
    }
}

__global__ void k_scan(const float* __restrict__ x) {
    __shared__ int wsum[8];
    __shared__ int sprefix;
    int b = blockIdx.x, t = threadIdx.x;
    int i = b * 256 + t;
    int lane = t & 31, w = t >> 5;
    int v = (i < NN) ? g_deg[i] : 0;
    int s = v;
#pragma unroll
    for (int o = 1; o < 32; o <<= 1) {
        int u = __shfl_up_sync(~0u, s, o);
        if (lane >= o) s += u;
    }
    if (lane == 31) wsum[w] = s;
    __syncthreads();
    if (w == 0) {
        int ws = (lane < 8) ? wsum[lane] : 0;
#pragma unroll
        for (int o = 1; o < 8; o <<= 1) {
            int u = __shfl_up_sync(0xffu, ws, o);
            if (lane >= o) ws += u;
        }
        if (lane < 8) wsum[lane] = ws;
    }
    __syncthreads();
    int total = wsum[7];
    if (t == 0) {
        if (b == 0) {
            atomicExch(&g_blkDesc[0], ((unsigned long long)total << 2) | 2ULL);
            sprefix = 0;
        } else {
            atomicExch(&g_blkDesc[b], ((unsigned long long)total << 2) | 1ULL);
            int run = 0;
            for (int j = b - 1; j >= 0; j--) {
                unsigned long long d;
                do { d = *((volatile unsigned long long*)&g_blkDesc[j]); } while ((d & 3ULL) == 0ULL);
                run += (int)(d >> 2);
                if ((d & 3ULL) == 2ULL) break;
            }
            sprefix = run;
            atomicExch(&g_blkDesc[b], ((unsigned long long)(total + run) << 2) | 2ULL);
        }
    }
    __syncthreads();
    int excl = sprefix + (w > 0 ? wsum[w - 1] : 0) + (s - v);
    if (i < NN) {
        g_rowptr[i] = excl;
        g_cursor[i] = excl;
        float di = rsqrtf((float)v + 1.0f);  // +1 self loop
        g_dinv[i] = di;
        __half2* xo = (__half2*)g_xs16;
        float f[10];
#pragma unroll
        for (int c = 0; c < DIN; c++) f[c] = di * x[i * DIN + c];
        f[9] = 0.f;
#pragma unroll
        for (int j = 0; j < 5; j++)
            xo[i * 8 + j] = __floats2half2_rn(f[2 * j], f[2 * j + 1]);
#pragma unroll
        for (int j = 5; j < 8; j++)
            xo[i * 8 + j] = __floats2half2_rn(0.f, 0.f);
    }
    if (i == 0) g_rowptr[NN] = EE;
}

__global__ void k_fill(const int* __restrict__ row, const int* __restrict__ col) {
    int i = blockIdx.x * blockDim.x + threadIdx.x;
    if (i < NN) g_deg[i] = 0;
    long long base = (long long)i * 16;
    if (base < EE) {
        const int4* r4 = reinterpret_cast<const int4*>(row) + i * 4;
        const int4* c4 = reinterpret_cast<const int4*>(col) + i * 4;
#pragma unroll
        for (int j = 0; j < 4; j++) {
            int4 r = r4[j];
            int4 c = c4[j];
            g_csrsrc[atomicAdd(&g_cursor[c.x], 1)] = r.x;
            g_csrsrc[atomicAdd(&g_cursor[c.y], 1)] = r.y;
            g_csrsrc[atomicAdd(&g_cursor[c.z], 1)] = r.z;
            g_csrsrc[atomicAdd(&g_cursor[c.w], 1)] = r.w;
        }
    }
}

// fp32-path accumulate into named accumulator array
#define ACC8V(acc, q)                                                        \
    { float2 f;                                                              \
      f = __half22float2(H2C((q).x)); acc[0] += f.x; acc[1] += f.y;          \
      f = __half22float2(H2C((q).y)); acc[2] += f.x; acc[3] += f.y;          \
      f = __half22float2(H2C((q).z)); acc[4] += f.x; acc[5] += f.y;          \
      f = __half22float2(H2C((q).w)); acc[6] += f.x; acc[7] += f.y; }

// fp16 tree (q0+q1)+(q2+q3) then flush into acc[0..7]
#define ACCTREE4V(acc, q0, q1, q2, q3)                                       \
    { __half2 t0 = __hadd2(H2C((q0).x), H2C((q1).x));                        \
      __half2 t1 = __hadd2(H2C((q0).y), H2C((q1).y));                        \
      __half2 t2 = __hadd2(H2C((q0).z), H2C((q1).z));                        \
      __half2 t3 = __hadd2(H2C((q0).w), H2C((q1).w));                        \
      __half2 u0 = __hadd2(H2C((q2).x), H2C((q3).x));                        \
      __half2 u1 = __hadd2(H2C((q2).y), H2C((q3).y));                        \
      __half2 u2 = __hadd2(H2C((q2).z), H2C((q3).z));                        \
      __half2 u3 = __hadd2(H2C((q2).w), H2C((q3).w));                        \
      __half2 v0 = __hadd2(t0, u0);                                          \
      __half2 v1 = __hadd2(t1, u1);                                          \
      __half2 v2 = __hadd2(t2, u2);                                          \
      __half2 v3 = __hadd2(t3, u3);                                          \
      float2 f;                                                              \
      f = __half22float2(v0); acc[0] += f.x; acc[1] += f.y;                  \
      f = __half22float2(v1); acc[2] += f.x; acc[3] += f.y;                  \
      f = __half22float2(v2); acc[4] += f.x; acc[5] += f.y;                  \
      f = __half22float2(v3); acc[6] += f.x; acc[7] += f.y; }

// self-term + dinv scale, uint4 of halves into acc
#define SELFSCALE(acc, qs, di)                                               \
    { float2 f;                                                              \
      f = __half22float2(H2C((qs).x)); acc[0] = di * (acc[0] + f.x); acc[1] = di * (acc[1] + f.y); \
      f = __half22float2(H2C((qs).y)); acc[2] = di * (acc[2] + f.x); acc[3] = di * (acc[3] + f.y); \
      f = __half22float2(H2C((qs).z)); acc[4] = di * (acc[4] + f.x); acc[5] = di * (acc[5] + f.y); \
      f = __half22float2(H2C((qs).w)); acc[6] = di * (acc[6] + f.x); acc[7] = di * (acc[7] + f.y); }

// ------------------- fused layer 0: 2-node interleaved predicated gather + FFMA GEMM -------------------

__global__ void __launch_bounds__(512) k_layer0(const float* __restrict__ W0,
                                                const float* __restrict__ b0,
                                                __half2* __restrict__ uout) {
    __shared__ float sW[DIN * DD];
    __shared__ float sHT[16][68];   // [feature][node]
    __shared__ float sB[DD];
    __shared__ float sDI[64];
    int tid = threadIdx.x;
    int nodeBase = blockIdx.x * 64;
    for (int i = tid; i < DIN * DD; i += 512) sW[i] = W0[i];
    if (tid < DD) sB[tid] = b0[tid];
    int unit = tid >> 4;     // 0..31, each handles nodes 2*unit, 2*unit+1
    int sl = tid & 15;
    int g = sl >> 1;         // neighbor slot 0..7
    int c2 = sl & 1;         // which uint4 of the 32B row
    const uint4* xs4 = (const uint4*)g_xs16;

    int locA = unit * 2, locB = unit * 2 + 1;
    int nodeA = nodeBase + locA, nodeB = nodeBase + locB;
    float accA[8] = {0, 0, 0, 0, 0, 0, 0, 0};
    float accB[8] = {0, 0, 0, 0, 0, 0, 0, 0};
    float diA = 0.f, diB = 0.f;
    int eA = 0, eA1 = 0, eB = 0, eB1 = 0;
    if (nodeA < NN) { diA = g_dinv[nodeA]; eA = g_rowptr[nodeA]; eA1 = g_rowptr[nodeA + 1]; }
    if (nodeB < NN) { diB = g_dinv[nodeB]; eB = g_rowptr[nodeB]; eB1 = g_rowptr[nodeB + 1]; }
    eA += g; eB += g;
    while (eA < eA1 || eB < eB1) {
        if (eA < eA1) { uint4 q = xs4[g_csrsrc[eA] * 2 + c2]; ACC8V(accA, q); }
        if (eB < eB1) { uint4 q = xs4[g_csrsrc[eB] * 2 + c2]; ACC8V(accB, q); }
        eA += 8; eB += 8;
    }
#pragma unroll
    for (int o = 8; o >= 2; o >>= 1) {
#pragma unroll
        for (int j = 0; j < 8; j++) {
            accA[j] += __shfl_down_sync(~0u, accA[j], o, 16);
            accB[j] += __shfl_down_sync(~0u, accB[j], o, 16);
        }
    }
    if (sl < 2) {  // sl == c2
        if (nodeA < NN) { uint4 qs = xs4[nodeA * 2 + sl]; SELFSCALE(accA, qs, diA); }
        if (nodeB < NN) { uint4 qs = xs4[nodeB * 2 + sl]; SELFSCALE(accB, qs, diB); }
#pragma unroll
        for (int j = 0; j < 8; j++) {
            sHT[8 * sl + j][locA] = accA[j];
            sHT[8 * sl + j][locB] = accB[j];
        }
        if (sl == 0) { sDI[locA] = diA; sDI[locB] = diB; }
    }
    __syncthreads();
    int dq = tid & 31, nq = tid >> 5;
    float acc[4][2];
#pragma unroll
    for (int i = 0; i < 4; i++) { acc[i][0] = sB[2 * dq]; acc[i][1] = sB[2 * dq + 1]; }
#pragma unroll
    for (int k = 0; k < DIN; k++) {
        float4 h4 = *reinterpret_cast<const float4*>(&sHT[k][4 * nq]);
        float2 w2 = *reinterpret_cast<const float2*>(&sW[k * DD + 2 * dq]);
        acc[0][0] += h4.x * w2.x; acc[0][1] += h4.x * w2.y;
        acc[1][0] += h4.y * w2.x; acc[1][1] += h4.y * w2.y;
        acc[2][0] += h4.z * w2.x; acc[2][1] += h4.z * w2.y;
        acc[3][0] += h4.w * w2.x; acc[3][1] += h4.w * w2.y;
    }
#pragma unroll
    for (int i = 0; i < 4; i++) {
        int n = nodeBase + 4 * nq + i;
        if (n < NN) {
            float sc = sDI[4 * nq + i];
            uout[n * 32 + dq] = __floats2half2_rn(sc * tanh_a(acc[i][0]),
                                                  sc * tanh_a(acc[i][1]));
        }
    }
}

// ------------------- fused layer: 2-node interleaved fp16-tree gather + fp16 MMA GEMM -------------------

template <bool OUT_HALF, bool PRESCALE>
__global__ void __launch_bounds__(512, 3) k_layer(const __half2* __restrict__ uin,
                                                  const float* __restrict__ W,
                                                  const float* __restrict__ bias,
                                                  void* __restrict__ uout) {
    __shared__ __half sA[64][72];    // agg tile fp16, stride 72 (ldmatrix conflict-free)
    __shared__ __half sBW[64][72];   // W fp16 [k][col]
    __shared__ float  sB[DD];
    __shared__ float  sDI[64];
    int tid = threadIdx.x;
    int nodeBase = blockIdx.x * 64;
    for (int i = tid; i < DD * DD; i += 512)
        sBW[i >> 6][i & 63] = __float2half(W[i]);
    if (tid < DD) sB[tid] = bias[tid];
    int unit = tid >> 4;    // 0..31; handles nodes 2*unit, 2*unit+1
    int sl = tid & 15;
    int g8 = sl >> 3;       // neighbor slot (0/1)
    int c8 = sl & 7;        // uint4 col (half-cols 8c8..8c8+7)
    const uint4* u4 = (const uint4*)uin;

    int locA = unit * 2, locB = unit * 2 + 1;
    int nodeA = nodeBase + locA, nodeB = nodeBase + locB;
    float aA[8] = {0, 0, 0, 0, 0, 0, 0, 0};
    float aB[8] = {0, 0, 0, 0, 0, 0, 0, 0};
    float diA = 0.f, diB = 0.f;
    int eA = 0, eA1 = 0, eB = 0, eB1 = 0;
    if (nodeA < NN) { diA = g_dinv[nodeA]; eA = g_rowptr[nodeA]; eA1 = g_rowptr[nodeA + 1]; }
    if (nodeB < NN) { diB = g_dinv[nodeB]; eB = g_rowptr[nodeB]; eB1 = g_rowptr[nodeB + 1]; }
    // interleaved main loop: 8 edges per node per iter, both nodes in flight
    while (eA + 8 <= eA1 && eB + 8 <= eB1) {
        int sA0 = g_csrsrc[eA + g8];
        int sA1 = g_csrsrc[eA + 2 + g8];
        int sA2 = g_csrsrc[eA + 4 + g8];
        int sA3 = g_csrsrc[eA + 6 + g8];
        int sB0 = g_csrsrc[eB + g8];
        int sB1 = g_csrsrc[eB + 2 + g8];
        int sB2 = g_csrsrc[eB + 4 + g8];
        int sB3 = g_csrsrc[eB + 6 + g8];
        uint4 qA0 = u4[sA0 * 8 + c8];
        uint4 qA1 = u4[sA1 * 8 + c8];
        uint4 qA2 = u4[sA2 * 8 + c8];
        uint4 qA3 = u4[sA3 * 8 + c8];
        uint4 qB0 = u4[sB0 * 8 + c8];
        uint4 qB1 = u4[sB1 * 8 + c8];
        uint4 qB2 = u4[sB2 * 8 + c8];
        uint4 qB3 = u4[sB3 * 8 + c8];
        ACCTREE4V(aA, qA0, qA1, qA2, qA3);
        ACCTREE4V(aB, qB0, qB1, qB2, qB3);
        eA += 8; eB += 8;
    }
    // drain whichever node has 8+ edges left
    for (; eA + 8 <= eA1; eA += 8) {
        int s0 = g_csrsrc[eA + g8];
        int s1 = g_csrsrc[eA + 2 + g8];
        int s2 = g_csrsrc[eA + 4 + g8];
        int s3 = g_csrsrc[eA + 6 + g8];
        uint4 q0 = u4[s0 * 8 + c8];
        uint4 q1 = u4[s1 * 8 + c8];
        uint4 q2 = u4[s2 * 8 + c8];
        uint4 q3 = u4[s3 * 8 + c8];
        ACCTREE4V(aA, q0, q1, q2, q3);
    }
    for (; eB + 8 <= eB1; eB += 8) {
        int s0 = g_csrsrc[eB + g8];
        int s1 = g_csrsrc[eB + 2 + g8];
        int s2 = g_csrsrc[eB + 4 + g8];
        int s3 = g_csrsrc[eB + 6 + g8];
        uint4 q0 = u4[s0 * 8 + c8];
        uint4 q1 = u4[s1 * 8 + c8];
        uint4 q2 = u4[s2 * 8 + c8];
        uint4 q3 = u4[s3 * 8 + c8];
        ACCTREE4V(aB, q0, q1, q2, q3);
    }
    // predicated tails (each lane group covers its parity)
    for (int e2 = eA + g8; e2 < eA1; e2 += 2) {
        uint4 q = u4[g_csrsrc[e2] * 8 + c8]; ACC8V(aA, q);
    }
    for (int e2 = eB + g8; e2 < eB1; e2 += 2) {
        uint4 q = u4[g_csrsrc[e2] * 8 + c8]; ACC8V(aB, q);
    }
    // merge the two neighbor-slot groups (within 16-lane unit)
#pragma unroll
    for (int j = 0; j < 8; j++) {
        aA[j] += __shfl_down_sync(~0u, aA[j], 8, 16);
        aB[j] += __shfl_down_sync(~0u, aB[j], 8, 16);
    }
    if (sl < 8) {   // sl == c8 here
        if (nodeA < NN) { uint4 qs = u4[nodeA * 8 + c8]; SELFSCALE(aA, qs, diA); }
        if (nodeB < NN) { uint4 qs = u4[nodeB * 8 + c8]; SELFSCALE(aB, qs, diB); }
        __half2 h0 = __floats2half2_rn(aA[0], aA[1]);
        __half2 h1 = __floats2half2_rn(aA[2], aA[3]);
        __half2 h2 = __floats2half2_rn(aA[4], aA[5]);
        __half2 h3 = __floats2half2_rn(aA[6], aA[7]);
        uint4 q;
        q.x = *reinterpret_cast<unsigned int*>(&h0);
        q.y = *reinterpret_cast<unsigned int*>(&h1);
        q.z = *reinterpret_cast<unsigned int*>(&h2);
        q.w = *reinterpret_cast<unsigned int*>(&h3);
        *reinterpret_cast<uint4*>(&sA[locA][c8 * 8]) = q;
        h0 = __floats2half2_rn(aB[0], aB[1]);
        h1 = __floats2half2_rn(aB[2], aB[3]);
        h2 = __floats2half2_rn(aB[4], aB[5]);
        h3 = __floats2half2_rn(aB[6], aB[7]);
        q.x = *reinterpret_cast<unsigned int*>(&h0);
        q.y = *reinterpret_cast<unsigned int*>(&h1);
        q.z = *reinterpret_cast<unsigned int*>(&h2);
        q.w = *reinterpret_cast<unsigned int*>(&h3);
        *reinterpret_cast<uint4*>(&sA[locB][c8 * 8]) = q;
        if (sl == 0) { sDI[locA] = diA; sDI[locB] = diB; }
    }
    __syncthreads();
    // MMA: warp (mi,ni) computes nodes 16mi..16mi+15 x cols 16ni..16ni+15
    int lane = tid & 31;
    int wid = tid >> 5;
    int mi = wid >> 2, ni = wid & 3;
    float c0[4] = {0.f, 0.f, 0.f, 0.f};
    float c1[4] = {0.f, 0.f, 0.f, 0.f};
    unsigned int aBase = smem_u32(&sA[16 * mi + (lane & 15)][(lane >> 4) * 8]);
    unsigned int bBase = smem_u32(&sBW[lane & 15][16 * ni + ((lane >> 4) << 3)]);
#pragma unroll
    for (int kk = 0; kk < 4; kk++) {
        unsigned int a0, a1, a2, a3, b0, b1, b2, b3;
        ldmx4(a0, a1, a2, a3, aBase + kk * 32);          // +16 halves in k
        ldmx4t(b0, b1, b2, b3, bBase + kk * 16 * 144);   // +16 rows of 144 B
        mma16816(c0, a0, a1, a2, a3, b0, b1);
        mma16816(c1, a0, a1, a2, a3, b2, b3);
    }
    int r0 = 16 * mi + (lane >> 2);
    int cb0 = 16 * ni + (lane & 3) * 2;
#pragma unroll
    for (int t2 = 0; t2 < 2; t2++) {
        const float* cc = t2 ? c1 : c0;
        int cb = cb0 + t2 * 8;
        float bx = sB[cb], by = sB[cb + 1];
#pragma unroll
        for (int rh = 0; rh < 2; rh++) {
            int r = r0 + rh * 8;
            int n = nodeBase + r;
            if (n < NN) {
                float v0 = cc[2 * rh] + bx;
                float v1 = cc[2 * rh + 1] + by;
                if (OUT_HALF) {
                    float sc = PRESCALE ? sDI[r] : 1.0f;
                    ((__half2*)uout)[n * 32 + (cb >> 1)] =
                        __floats2half2_rn(sc * tanh_a(v0), sc * tanh_a(v1));
                } else {
                    ((float2*)uout)[n * 32 + (cb >> 1)] =
                        make_float2(tanh_a(v0), tanh_a(v1));
                }
            }
        }
    }
}

// ------------------- pooling + head -------------------
__global__ void k_pool(const float* __restrict__ h, const float* __restrict__ Wout,
                       const float* __restrict__ bout, float* __restrict__ out) {
    int g = (blockIdx.x * blockDim.x + threadIdx.x) >> 5;
    int lid = threadIdx.x & 31;
    if (g >= GG) return;
    long long gs = (long long)g * NN;
    int start = (int)((gs + GG - 1) / GG);
    int end = (int)((gs + NN + GG - 1) / GG);
    if (end > NN) end = NN;
    const float2* h2 = (const float2*)h;
    float2 mx = make_float2(-INFINITY, -INFINITY);
    float2 sm = make_float2(0.f, 0.f);
    for (int i = start; i < end; i++) {
        float2 v = h2[i * 32 + lid];
        mx.x = fmaxf(mx.x, v.x);
        mx.y = fmaxf(mx.y, v.y);
        sm.x += v.x;
        sm.y += v.y;
    }
    int cnt = end - start; if (cnt < 1) cnt = 1;
    float inv = 1.0f / (float)cnt;
    const float2* w2 = (const float2*)Wout;
    float2 wmx = w2[lid];
    float2 wmn = w2[32 + lid];
    float v = mx.x * wmx.x + mx.y * wmx.y
            + (sm.x * inv) * wmn.x + (sm.y * inv) * wmn.y;
#pragma unroll
    for (int o = 16; o; o >>= 1) v += __shfl_down_sync(0xffffffffu, v, o);
    if (lid == 0) out[g] = v + bout[0];
}

// ------------------- launch -------------------

extern "C" void kernel_launch(void* const* d_in, const int* in_sizes, int n_in,
                              void* d_out, int out_size) {
    const float* x    = (const float*)d_in[0];
    const int*   ei   = (const int*)d_in[1];
    const float* W0   = (const float*)d_in[3];
    const float* b0   = (const float*)d_in[4];
    const float* W1   = (const float*)d_in[5];
    const float* b1   = (const float*)d_in[6];
    const float* W2   = (const float*)d_in[7];
    const float* b2   = (const float*)d_in[8];
    const float* W3   = (const float*)d_in[9];
    const float* b3   = (const float*)d_in[10];
    const float* Wout = (const float*)d_in[11];
    const float* bout = (const float*)d_in[12];
    float* out = (float*)d_out;

    const int* erow = ei;        // sources
    const int* ecol = ei + EE;   // destinations

    float *hA, *hB;
    cudaGetSymbolAddress((void**)&hA, g_hA);
    cudaGetSymbolAddress((void**)&hB, g_hB);

    int eB16 = (EE / 16 + 255) / 256;  // 196: 16 edges/thread
    int gB = (NN + 63) / 64;           // 782
    int pB = (GG * 32 + 255) / 256;

    k_hist<<<eB16, 256>>>(ecol);
    k_scan<<<NBLK, 256>>>(x);
    k_fill<<<eB16, 256>>>(erow, ecol);

    k_layer0<<<gB, 512>>>(W0, b0, (__half2*)hA);
    k_layer<true, true><<<gB, 512>>>((const __half2*)hA, W1, b1, hB);
    k_layer<true, true><<<gB, 512>>>((const __half2*)hB, W2, b2, hA);
    k_layer<false, false><<<gB, 512>>>((const __half2*)hA, W3, b3, hB);

    k_pool<<<pB, 256>>>(hB, Wout, bout, out);
}

// round 15
// speedup vs baseline: 1.2286x; 1.2286x over previous
#include <cuda_runtime.h>
#include <cuda_fp16.h>
#include <math.h>

#define NN 50000
#define EE 800000
#define GG 1024
#define DD 64
#define DIN 9
#define NBLK ((NN + 255) / 256)    // 196

// ---- scratch ----
__device__ int   g_deg[NN];        // all-zero at entry; re-zeroed in k_fill each call
__device__ float g_dinv[NN];
__device__ int   g_rowptr[NN + 1];
__device__ int   g_cursor[NN];
__device__ int   g_csrsrc[EE];
__device__ unsigned long long g_blkDesc[NBLK];  // zeroed in k_hist each call
__device__ uint4 g_xs16[NN * 2];   // fp16 input features, 16 halves/node (9 used)
__device__ float g_hA[NN * DD];
__device__ float g_hB[NN * DD];

__device__ __forceinline__ float tanh_a(float x) {
    float y;
    asm("tanh.approx.f32 %0, %1;" : "=f"(y) : "f"(x));
    return y;
}
__device__ __forceinline__ unsigned int smem_u32(const void* p) {
    return (unsigned int)__cvta_generic_to_shared(p);
}
__device__ __forceinline__ void ldmx4(unsigned int& r0, unsigned int& r1,
                                      unsigned int& r2, unsigned int& r3, unsigned int a) {
    asm volatile("ldmatrix.sync.aligned.m8n8.x4.shared.b16 {%0,%1,%2,%3}, [%4];"
                 : "=r"(r0), "=r"(r1), "=r"(r2), "=r"(r3) : "r"(a));
}
__device__ __forceinline__ void ldmx4t(unsigned int& r0, unsigned int& r1,
                                       unsigned int& r2, unsigned int& r3, unsigned int a) {
    asm volatile("ldmatrix.sync.aligned.m8n8.x4.trans.shared.b16 {%0,%1,%2,%3}, [%4];"
                 : "=r"(r0), "=r"(r1), "=r"(r2), "=r"(r3) : "r"(a));
}
__device__ __forceinline__ void mma16816(float* c, unsigned int a0, unsigned int a1,
                                         unsigned int a2, unsigned int a3,
                                         unsigned int b0, unsigned int b1) {
    asm volatile("mma.sync.aligned.m16n8k16.row.col.f32.f16.f16.f32 "
                 "{%0,%1,%2,%3}, {%4,%5,%6,%7}, {%8,%9}, {%0,%1,%2,%3};"
                 : "+f"(c[0]), "+f"(c[1]), "+f"(c[2]), "+f"(c[3])
                 : "r"(a0), "r"(a1), "r"(a2), "r"(a3), "r"(b0), "r"(b1));
}

#define H2C(p) (*(const __half2*)&(p))

// ------------------- preprocessing -------------------

__global__ void k_hist(const int* __restrict__ col) {
    int i = blockIdx.x * blockDim.x + threadIdx.x;
    if (i < NBLK) g_blkDesc[i] = 0ULL;
    long long base = (long long)i * 16;
    if (base < EE) {
        const int4* c4 = reinterpret_cast<const int4*>(col) + i * 4;
        int4 a = c4[0], b = c4[1], c = c4[2], d = c4[3];
        atomicAdd(&g_deg[a.x], 1); atomicAdd(&g_deg[a.y], 1);
        atomicAdd(&g_deg[a.z], 1); atomicAdd(&g_deg[a.w], 1);
        atomicAdd(&g_deg[b.x], 1); atomicAdd(&g_deg[b.y], 1);
        atomicAdd(&g_deg[b.z], 1); atomicAdd(&g_deg[b.w], 1);
        atomicAdd(&g_deg[c.x], 1); atomicAdd(&g_deg[c.y], 1);
        atomicAdd(&g_deg[c.z], 1); atomicAdd(&g_deg[c.w], 1);
        atomicAdd(&g_deg[d.x], 1); atomicAdd(&g_deg[d.y], 1);
        atomicAdd(&g_deg[d.z], 1); atomicAdd(&g_deg[d.w], 1);
    }
}

__global__ void k_scan(const float* __restrict__ x) {
    __shared__ int wsum[8];
    __shared__ int sprefix;
    int b = blockIdx.x, t = threadIdx.x;
    int i = b * 256 + t;
    int lane = t & 31, w = t >> 5;
    int v = (i < NN) ? g_deg[i] : 0;
    int s = v;
#pragma unroll
    for (int o = 1; o < 32; o <<= 1) {
        int u = __shfl_up_sync(~0u, s, o);
        if (lane >= o) s += u;
    }
    if (lane == 31) wsum[w] = s;
    __syncthreads();
    if (w == 0) {
        int ws = (lane < 8) ? wsum[lane] : 0;
#pragma unroll
        for (int o = 1; o < 8; o <<= 1) {
            int u = __shfl_up_sync(0xffu, ws, o);
            if (lane >= o) ws += u;
        }
        if (lane < 8) wsum[lane] = ws;
    }
    __syncthreads();
    int total = wsum[7];
    if (t == 0) {
        if (b == 0) {
            atomicExch(&g_blkDesc[0], ((unsigned long long)total << 2) | 2ULL);
            sprefix = 0;
        } else {
            atomicExch(&g_blkDesc[b], ((unsigned long long)total << 2) | 1ULL);
            int run = 0;
            for (int j = b - 1; j >= 0; j--) {
                unsigned long long d;
                do { d = *((volatile unsigned long long*)&g_blkDesc[j]); } while ((d & 3ULL) == 0ULL);
                run += (int)(d >> 2);
                if ((d & 3ULL) == 2ULL) break;
            }
            sprefix = run;
            atomicExch(&g_blkDesc[b], ((unsigned long long)(total + run) << 2) | 2ULL);
        }
    }
    __syncthreads();
    int excl = sprefix + (w > 0 ? wsum[w - 1] : 0) + (s - v);
    if (i < NN) {
        g_rowptr[i] = excl;
        g_cursor[i] = excl;
        float di = rsqrtf((float)v + 1.0f);  // +1 self loop
        g_dinv[i] = di;
        __half2* xo = (__half2*)g_xs16;
        float f[10];
#pragma unroll
        for (int c = 0; c < DIN; c++) f[c] = di * x[i * DIN + c];
        f[9] = 0.f;
#pragma unroll
        for (int j = 0; j < 5; j++)
            xo[i * 8 + j] = __floats2half2_rn(f[2 * j], f[2 * j + 1]);
#pragma unroll
        for (int j = 5; j < 8; j++)
            xo[i * 8 + j] = __floats2half2_rn(0.f, 0.f);
    }
    if (i == 0) g_rowptr[NN] = EE;
}

__global__ void k_fill(const int* __restrict__ row, const int* __restrict__ col) {
    int i = blockIdx.x * blockDim.x + threadIdx.x;
    if (i < NN) g_deg[i] = 0;
    long long base = (long long)i * 16;
    if (base < EE) {
        const int4* r4 = reinterpret_cast<const int4*>(row) + i * 4;
        const int4* c4 = reinterpret_cast<const int4*>(col) + i * 4;
#pragma unroll
        for (int j = 0; j < 4; j++) {
            int4 r = r4[j];
            int4 c = c4[j];
            g_csrsrc[atomicAdd(&g_cursor[c.x], 1)] = r.x;
            g_csrsrc[atomicAdd(&g_cursor[c.y], 1)] = r.y;
            g_csrsrc[atomicAdd(&g_cursor[c.z], 1)] = r.z;
            g_csrsrc[atomicAdd(&g_cursor[c.w], 1)] = r.w;
        }
    }
}

// fp32-path accumulate: 8 half cols from a uint4 into a0..a7
#define ACC8(q)                                                              \
    { float2 f;                                                              \
      f = __half22float2(H2C((q).x)); a0 += f.x; a1 += f.y;                  \
      f = __half22float2(H2C((q).y)); a2 += f.x; a3 += f.y;                  \
      f = __half22float2(H2C((q).z)); a4 += f.x; a5 += f.y;                  \
      f = __half22float2(H2C((q).w)); a6 += f.x; a7 += f.y; }

// same into named accumulator array
#define ACC8V(acc, q)                                                        \
    { float2 f;                                                              \
      f = __half22float2(H2C((q).x)); acc[0] += f.x; acc[1] += f.y;          \
      f = __half22float2(H2C((q).y)); acc[2] += f.x; acc[3] += f.y;          \
      f = __half22float2(H2C((q).z)); acc[4] += f.x; acc[5] += f.y;          \
      f = __half22float2(H2C((q).w)); acc[6] += f.x; acc[7] += f.y; }

// fp16 tree (q0+q1)+(q2+q3) then flush to fp32 accumulators a0..a7
#define ACCTREE4(q0, q1, q2, q3)                                             \
    { __half2 t0 = __hadd2(H2C((q0).x), H2C((q1).x));                        \
      __half2 t1 = __hadd2(H2C((q0).y), H2C((q1).y));                        \
      __half2 t2 = __hadd2(H2C((q0).z), H2C((q1).z));                        \
      __half2 t3 = __hadd2(H2C((q0).w), H2C((q1).w));                        \
      __half2 u0 = __hadd2(H2C((q2).x), H2C((q3).x));                        \
      __half2 u1 = __hadd2(H2C((q2).y), H2C((q3).y));                        \
      __half2 u2 = __hadd2(H2C((q2).z), H2C((q3).z));                        \
      __half2 u3 = __hadd2(H2C((q2).w), H2C((q3).w));                        \
      __half2 v0 = __hadd2(t0, u0);                                          \
      __half2 v1 = __hadd2(t1, u1);                                          \
      __half2 v2 = __hadd2(t2, u2);                                          \
      __half2 v3 = __hadd2(t3, u3);                                          \
      float2 f;                                                              \
      f = __half22float2(v0); a0 += f.x; a1 += f.y;                          \
      f = __half22float2(v1); a2 += f.x; a3 += f.y;                          \
      f = __half22float2(v2); a4 += f.x; a5 += f.y;                          \
      f = __half22float2(v3); a6 += f.x; a7 += f.y; }

// self-term + dinv scale, uint4 of halves into acc array
#define SELFSCALE(acc, qs, di)                                               \
    { float2 f;                                                              \
      f = __half22float2(H2C((qs).x)); acc[0] = di * (acc[0] + f.x); acc[1] = di * (acc[1] + f.y); \
      f = __half22float2(H2C((qs).y)); acc[2] = di * (acc[2] + f.x); acc[3] = di * (acc[3] + f.y); \
      f = __half22float2(H2C((qs).z)); acc[4] = di * (acc[4] + f.x); acc[5] = di * (acc[5] + f.y); \
      f = __half22float2(H2C((qs).w)); acc[6] = di * (acc[6] + f.x); acc[7] = di * (acc[7] + f.y); }

// ------------------- fused layer 0: 2-node interleaved predicated gather + FFMA GEMM -------------------

__global__ void __launch_bounds__(512) k_layer0(const float* __restrict__ W0,
                                                const float* __restrict__ b0,
                                                __half2* __restrict__ uout) {
    __shared__ float sW[DIN * DD];
    __shared__ float sHT[16][68];   // [feature][node]
    __shared__ float sB[DD];
    __shared__ float sDI[64];
    int tid = threadIdx.x;
    int nodeBase = blockIdx.x * 64;
    for (int i = tid; i < DIN * DD; i += 512) sW[i] = W0[i];
    if (tid < DD) sB[tid] = b0[tid];
    int unit = tid >> 4;     // 0..31, each handles nodes 2*unit, 2*unit+1
    int sl = tid & 15;
    int g = sl >> 1;         // neighbor slot 0..7
    int c2 = sl & 1;         // which uint4 of the 32B row
    const uint4* xs4 = (const uint4*)g_xs16;

    int locA = unit * 2, locB = unit * 2 + 1;
    int nodeA = nodeBase + locA, nodeB = nodeBase + locB;
    float accA[8] = {0, 0, 0, 0, 0, 0, 0, 0};
    float accB[8] = {0, 0, 0, 0, 0, 0, 0, 0};
    float diA = 0.f, diB = 0.f;
    int eA = 0, eA1 = 0, eB = 0, eB1 = 0;
    if (nodeA < NN) { diA = g_dinv[nodeA]; eA = g_rowptr[nodeA]; eA1 = g_rowptr[nodeA + 1]; }
    if (nodeB < NN) { diB = g_dinv[nodeB]; eB = g_rowptr[nodeB]; eB1 = g_rowptr[nodeB + 1]; }
    eA += g; eB += g;
    while (eA < eA1 || eB < eB1) {
        if (eA < eA1) { uint4 q = xs4[g_csrsrc[eA] * 2 + c2]; ACC8V(accA, q); }
        if (eB < eB1) { uint4 q = xs4[g_csrsrc[eB] * 2 + c2]; ACC8V(accB, q); }
        eA += 8; eB += 8;
    }
#pragma unroll
    for (int o = 8; o >= 2; o >>= 1) {
#pragma unroll
        for (int j = 0; j < 8; j++) {
            accA[j] += __shfl_down_sync(~0u, accA[j], o, 16);
            accB[j] += __shfl_down_sync(~0u, accB[j], o, 16);
        }
    }
    if (sl < 2) {  // sl == c2
        if (nodeA < NN) { uint4 qs = xs4[nodeA * 2 + sl]; SELFSCALE(accA, qs, diA); }
        if (nodeB < NN) { uint4 qs = xs4[nodeB * 2 + sl]; SELFSCALE(accB, qs, diB); }
#pragma unroll
        for (int j = 0; j < 8; j++) {
            sHT[8 * sl + j][locA] = accA[j];
            sHT[8 * sl + j][locB] = accB[j];
        }
        if (sl == 0) { sDI[locA] = diA; sDI[locB] = diB; }
    }
    __syncthreads();
    int dq = tid & 31, nq = tid >> 5;
    float acc[4][2];
#pragma unroll
    for (int i = 0; i < 4; i++) { acc[i][0] = sB[2 * dq]; acc[i][1] = sB[2 * dq + 1]; }
#pragma unroll
    for (int k = 0; k < DIN; k++) {
        float4 h4 = *reinterpret_cast<const float4*>(&sHT[k][4 * nq]);
        float2 w2 = *reinterpret_cast<const float2*>(&sW[k * DD + 2 * dq]);
        acc[0][0] += h4.x * w2.x; acc[0][1] += h4.x * w2.y;
        acc[1][0] += h4.y * w2.x; acc[1][1] += h4.y * w2.y;
        acc[2][0] += h4.z * w2.x; acc[2][1] += h4.z * w2.y;
        acc[3][0] += h4.w * w2.x; acc[3][1] += h4.w * w2.y;
    }
#pragma unroll
    for (int i = 0; i < 4; i++) {
        int n = nodeBase + 4 * nq + i;
        if (n < NN) {
            float sc = sDI[4 * nq + i];
            uout[n * 32 + dq] = __floats2half2_rn(sc * tanh_a(acc[i][0]),
                                                  sc * tanh_a(acc[i][1]));
        }
    }
}

// ------------------- fused layer: scalar-index fp16-tree gather + fp16 MMA GEMM (R13) -------------------

template <bool OUT_HALF, bool PRESCALE>
__global__ void __launch_bounds__(512) k_layer(const __half2* __restrict__ uin,
                                               const float* __restrict__ W,
                                               const float* __restrict__ bias,
                                               void* __restrict__ uout) {
    __shared__ __half sA[64][72];    // agg tile fp16, stride 72 (ldmatrix conflict-free)
    __shared__ __half sBW[64][72];   // W fp16 [k][col]
    __shared__ float  sB[DD];
    __shared__ float  sDI[64];
    int tid = threadIdx.x;
    int nodeBase = blockIdx.x * 64;
    for (int i = tid; i < DD * DD; i += 512)
        sBW[i >> 6][i & 63] = __float2half(W[i]);
    if (tid < DD) sB[tid] = bias[tid];
    int w = tid >> 5, lid = tid & 31;
    int hw = lid >> 4;      // node of pair
    int sl = lid & 15;
    int g8 = sl >> 3;       // neighbor slot (0/1)
    int c8 = sl & 7;        // uint4 col (half-cols 8c8..8c8+7)
    const uint4* u4 = (const uint4*)uin;
#pragma unroll
    for (int pass = 0; pass < 2; pass++) {
        int local = w * 4 + pass * 2 + hw;
        int node = nodeBase + local;
        float a0 = 0.f, a1 = 0.f, a2 = 0.f, a3 = 0.f;
        float a4 = 0.f, a5 = 0.f, a6 = 0.f, a7 = 0.f;
        float di = 0.f;
        if (node < NN) {
            di = g_dinv[node];
            int e = g_rowptr[node], e1 = g_rowptr[node + 1];
            // 8 edges per iter, scalar (coalesced) index loads, no alignment needed
            for (; e + 8 <= e1; e += 8) {
                int s0 = g_csrsrc[e + g8];
                int s1 = g_csrsrc[e + 2 + g8];
                int s2 = g_csrsrc[e + 4 + g8];
                int s3 = g_csrsrc[e + 6 + g8];
                uint4 q0 = u4[s0 * 8 + c8];
                uint4 q1 = u4[s1 * 8 + c8];
                uint4 q2 = u4[s2 * 8 + c8];
                uint4 q3 = u4[s3 * 8 + c8];
                ACCTREE4(q0, q1, q2, q3);
            }
            // predicated tail: each lane group covers its parity
            for (int e2 = e + g8; e2 < e1; e2 += 2) {
                uint4 q = u4[g_csrsrc[e2] * 8 + c8]; ACC8(q);
            }
        }
        // merge the two neighbor-slot groups
        a0 += __shfl_down_sync(~0u, a0, 8, 16);
        a1 += __shfl_down_sync(~0u, a1, 8, 16);
        a2 += __shfl_down_sync(~0u, a2, 8, 16);
        a3 += __shfl_down_sync(~0u, a3, 8, 16);
        a4 += __shfl_down_sync(~0u, a4, 8, 16);
        a5 += __shfl_down_sync(~0u, a5, 8, 16);
        a6 += __shfl_down_sync(~0u, a6, 8, 16);
        a7 += __shfl_down_sync(~0u, a7, 8, 16);
        if (sl < 8) {
            if (node < NN) {
                uint4 qs = u4[node * 8 + c8];
                float2 f;
                f = __half22float2(H2C(qs.x)); a0 = di * (a0 + f.x); a1 = di * (a1 + f.y);
                f = __half22float2(H2C(qs.y)); a2 = di * (a2 + f.x); a3 = di * (a3 + f.y);
                f = __half22float2(H2C(qs.z)); a4 = di * (a4 + f.x); a5 = di * (a5 + f.y);
                f = __half22float2(H2C(qs.w)); a6 = di * (a6 + f.x); a7 = di * (a7 + f.y);
            }
            __half2 h0 = __floats2half2_rn(a0, a1);
            __half2 h1 = __floats2half2_rn(a2, a3);
            __half2 h2 = __floats2half2_rn(a4, a5);
            __half2 h3 = __floats2half2_rn(a6, a7);
            uint4 q;
            q.x = *reinterpret_cast<unsigned int*>(&h0);
            q.y = *reinterpret_cast<unsigned int*>(&h1);
            q.z = *reinterpret_cast<unsigned int*>(&h2);
            q.w = *reinterpret_cast<unsigned int*>(&h3);
            *reinterpret_cast<uint4*>(&sA[local][c8 * 8]) = q;
            if (c8 == 0) sDI[local] = di;
        }
    }
    __syncthreads();
    // MMA: warp (mi,ni) computes nodes 16mi..16mi+15 x cols 16ni..16ni+15
    int lane = tid & 31;
    int wid = tid >> 5;
    int mi = wid >> 2, ni = wid & 3;
    float c0[4] = {0.f, 0.f, 0.f, 0.f};
    float c1[4] = {0.f, 0.f, 0.f, 0.f};
    unsigned int aBase = smem_u32(&sA[16 * mi + (lane & 15)][(lane >> 4) * 8]);
    unsigned int bBase = smem_u32(&sBW[lane & 15][16 * ni + ((lane >> 4) << 3)]);
#pragma unroll
    for (int kk = 0; kk < 4; kk++) {
        unsigned int a0, a1, a2, a3, b0, b1, b2, b3;
        ldmx4(a0, a1, a2, a3, aBase + kk * 32);          // +16 halves in k
        ldmx4t(b0, b1, b2, b3, bBase + kk * 16 * 144);   // +16 rows of 144 B
        mma16816(c0, a0, a1, a2, a3, b0, b1);
        mma16816(c1, a0, a1, a2, a3, b2, b3);
    }
    int r0 = 16 * mi + (lane >> 2);
    int cb0 = 16 * ni + (lane & 3) * 2;
#pragma unroll
    for (int t2 = 0; t2 < 2; t2++) {
        const float* cc = t2 ? c1 : c0;
        int cb = cb0 + t2 * 8;
        float bx = sB[cb], by = sB[cb + 1];
#pragma unroll
        for (int rh = 0; rh < 2; rh++) {
            int r = r0 + rh * 8;
            int n = nodeBase + r;
            if (n < NN) {
                float v0 = cc[2 * rh] + bx;
                float v1 = cc[2 * rh + 1] + by;
                if (OUT_HALF) {
                    float sc = PRESCALE ? sDI[r] : 1.0f;
                    ((__half2*)uout)[n * 32 + (cb >> 1)] =
                        __floats2half2_rn(sc * tanh_a(v0), sc * tanh_a(v1));
                } else {
                    ((float2*)uout)[n * 32 + (cb >> 1)] =
                        make_float2(tanh_a(v0), tanh_a(v1));
                }
            }
        }
    }
}

// ------------------- pooling + head -------------------
__global__ void k_pool(const float* __restrict__ h, const float* __restrict__ Wout,
                       const float* __restrict__ bout, float* __restrict__ out) {
    int g = (blockIdx.x * blockDim.x + threadIdx.x) >> 5;
    int lid = threadIdx.x & 31;
    if (g >= GG) return;
    long long gs = (long long)g * NN;
    int start = (int)((gs + GG - 1) / GG);
    int end = (int)((gs + NN + GG - 1) / GG);
    if (end > NN) end = NN;
    const float2* h2 = (const float2*)h;
    float2 mx = make_float2(-INFINITY, -INFINITY);
    float2 sm = make_float2(0.f, 0.f);
    for (int i = start; i < end; i++) {
        float2 v = h2[i * 32 + lid];
        mx.x = fmaxf(mx.x, v.x);
        mx.y = fmaxf(mx.y, v.y);
        sm.x += v.x;
        sm.y += v.y;
    }
    int cnt = end - start; if (cnt < 1) cnt = 1;
    float inv = 1.0f / (float)cnt;
    const float2* w2 = (const float2*)Wout;
    float2 wmx = w2[lid];
    float2 wmn = w2[32 + lid];
    float v = mx.x * wmx.x + mx.y * wmx.y
            + (sm.x * inv) * wmn.x + (sm.y * inv) * wmn.y;
#pragma unroll
    for (int o = 16; o; o >>= 1) v += __shfl_down_sync(0xffffffffu, v, o);
    if (lid == 0) out[g] = v + bout[0];
}

// ------------------- launch -------------------

extern "C" void kernel_launch(void* const* d_in, const int* in_sizes, int n_in,
                              void* d_out, int out_size) {
    const float* x    = (const float*)d_in[0];
    const int*   ei   = (const int*)d_in[1];
    const float* W0   = (const float*)d_in[3];
    const float* b0   = (const float*)d_in[4];
    const float* W1   = (const float*)d_in[5];
    const float* b1   = (const float*)d_in[6];
    const float* W2   = (const float*)d_in[7];
    const float* b2   = (const float*)d_in[8];
    const float* W3   = (const float*)d_in[9];
    const float* b3   = (const float*)d_in[10];
    const float* Wout = (const float*)d_in[11];
    const float* bout = (const float*)d_in[12];
    float* out = (float*)d_out;

    const int* erow = ei;        // sources
    const int* ecol = ei + EE;   // destinations

    float *hA, *hB;
    cudaGetSymbolAddress((void**)&hA, g_hA);
    cudaGetSymbolAddress((void**)&hB, g_hB);

    int eB16 = (EE / 16 + 255) / 256;  // 196: 16 edges/thread
    int gB = (NN + 63) / 64;           // 782
    int pB = (GG * 32 + 255) / 256;

    k_hist<<<eB16, 256>>>(ecol);
    k_scan<<<NBLK, 256>>>(x);
    k_fill<<<eB16, 256>>>(erow, ecol);

    k_layer0<<<gB, 512>>>(W0, b0, (__half2*)hA);
    k_layer<true, true><<<gB, 512>>>((const __half2*)hA, W1, b1, hB);
    k_layer<true, true><<<gB, 512>>>((const __half2*)hB, W2, b2, hA);
    k_layer<false, false><<<gB, 512>>>((const __half2*)hA, W3, b3, hB);

    k_pool<<<pB, 256>>>(hB, Wout, bout, out);
}

// round 16
// speedup vs baseline: 1.2698x; 1.0335x over previous
#include <cuda_runtime.h>
#include <cuda_fp16.h>
#include <math.h>

#define NN 50000
#define EE 800000
#define GG 1024
#define DD 64
#define DIN 9
#define NBLK ((NN + 255) / 256)    // 196

// ---- scratch ----
__device__ int   g_deg[NN];        // all-zero at entry; re-zeroed in k_fill each call
__device__ float g_dinv[NN];
__device__ int   g_rowptr[NN + 1];
__device__ int   g_cursor[NN];
__device__ int   g_csrsrc[EE];
__device__ unsigned long long g_blkDesc[NBLK];  // zeroed in k_hist each call
__device__ uint4 g_xs16[NN * 2];   // fp16 input features, 16 halves/node (9 used)
__device__ float g_hA[NN * DD];
__device__ float g_hB[NN * DD];

__device__ __forceinline__ float tanh_a(float x) {
    float y;
    asm("tanh.approx.f32 %0, %1;" : "=f"(y) : "f"(x));
    return y;
}
__device__ __forceinline__ unsigned int smem_u32(const void* p) {
    return (unsigned int)__cvta_generic_to_shared(p);
}
__device__ __forceinline__ void ldmx4(unsigned int& r0, unsigned int& r1,
                                      unsigned int& r2, unsigned int& r3, unsigned int a) {
    asm volatile("ldmatrix.sync.aligned.m8n8.x4.shared.b16 {%0,%1,%2,%3}, [%4];"
                 : "=r"(r0), "=r"(r1), "=r"(r2), "=r"(r3) : "r"(a));
}
__device__ __forceinline__ void ldmx4t(unsigned int& r0, unsigned int& r1,
                                       unsigned int& r2, unsigned int& r3, unsigned int a) {
    asm volatile("ldmatrix.sync.aligned.m8n8.x4.trans.shared.b16 {%0,%1,%2,%3}, [%4];"
                 : "=r"(r0), "=r"(r1), "=r"(r2), "=r"(r3) : "r"(a));
}
__device__ __forceinline__ void mma16816(float* c, unsigned int a0, unsigned int a1,
                                         unsigned int a2, unsigned int a3,
                                         unsigned int b0, unsigned int b1) {
    asm volatile("mma.sync.aligned.m16n8k16.row.col.f32.f16.f16.f32 "
                 "{%0,%1,%2,%3}, {%4,%5,%6,%7}, {%8,%9}, {%0,%1,%2,%3};"
                 : "+f"(c[0]), "+f"(c[1]), "+f"(c[2]), "+f"(c[3])
                 : "r"(a0), "r"(a1), "r"(a2), "r"(a3), "r"(b0), "r"(b1));
}

#define H2C(p) (*(const __half2*)&(p))

// ------------------- preprocessing (R13 config: 8 edges/thread) -------------------

__global__ void k_hist(const int* __restrict__ col) {
    int i = blockIdx.x * blockDim.x + threadIdx.x;
    if (i < NBLK) g_blkDesc[i] = 0ULL;
    long long base = (long long)i * 8;
    if (base < EE) {
        int4 a = reinterpret_cast<const int4*>(col)[i * 2];
        int4 b = reinterpret_cast<const int4*>(col)[i * 2 + 1];
        atomicAdd(&g_deg[a.x], 1); atomicAdd(&g_deg[a.y], 1);
        atomicAdd(&g_deg[a.z], 1); atomicAdd(&g_deg[a.w], 1);
        atomicAdd(&g_deg[b.x], 1); atomicAdd(&g_deg[b.y], 1);
        atomicAdd(&g_deg[b.z], 1); atomicAdd(&g_deg[b.w], 1);
    }
}

__global__ void k_scan(const float* __restrict__ x) {
    __shared__ int wsum[8];
    __shared__ int sprefix;
    int b = blockIdx.x, t = threadIdx.x;
    int i = b * 256 + t;
    int lane = t & 31, w = t >> 5;
    int v = (i < NN) ? g_deg[i] : 0;
    int s = v;
#pragma unroll
    for (int o = 1; o < 32; o <<= 1) {
        int u = __shfl_up_sync(~0u, s, o);
        if (lane >= o) s += u;
    }
    if (lane == 31) wsum[w] = s;
    __syncthreads();
    if (w == 0) {
        int ws = (lane < 8) ? wsum[lane] : 0;
#pragma unroll
        for (int o = 1; o < 8; o <<= 1) {
            int u = __shfl_up_sync(0xffu, ws, o);
            if (lane >= o) ws += u;
        }
        if (lane < 8) wsum[lane] = ws;
    }
    __syncthreads();
    int total = wsum[7];
    if (t == 0) {
        if (b == 0) {
            atomicExch(&g_blkDesc[0], ((unsigned long long)total << 2) | 2ULL);
            sprefix = 0;
        } else {
            atomicExch(&g_blkDesc[b], ((unsigned long long)total << 2) | 1ULL);
            int run = 0;
            for (int j = b - 1; j >= 0; j--) {
                unsigned long long d;
                do { d = *((volatile unsigned long long*)&g_blkDesc[j]); } while ((d & 3ULL) == 0ULL);
                run += (int)(d >> 2);
                if ((d & 3ULL) == 2ULL) break;
            }
            sprefix = run;
            atomicExch(&g_blkDesc[b], ((unsigned long long)(total + run) << 2) | 2ULL);
        }
    }
    __syncthreads();
    int excl = sprefix + (w > 0 ? wsum[w - 1] : 0) + (s - v);
    if (i < NN) {
        g_rowptr[i] = excl;
        g_cursor[i] = excl;
        float di = rsqrtf((float)v + 1.0f);  // +1 self loop
        g_dinv[i] = di;
        __half2* xo = (__half2*)g_xs16;
        float f[10];
#pragma unroll
        for (int c = 0; c < DIN; c++) f[c] = di * x[i * DIN + c];
        f[9] = 0.f;
#pragma unroll
        for (int j = 0; j < 5; j++)
            xo[i * 8 + j] = __floats2half2_rn(f[2 * j], f[2 * j + 1]);
#pragma unroll
        for (int j = 5; j < 8; j++)
            xo[i * 8 + j] = __floats2half2_rn(0.f, 0.f);
    }
    if (i == 0) g_rowptr[NN] = EE;
}

__global__ void k_fill(const int* __restrict__ row, const int* __restrict__ col) {
    int i = blockIdx.x * blockDim.x + threadIdx.x;
    if (i < NN) g_deg[i] = 0;
    long long base = (long long)i * 8;
    if (base < EE) {
        int4 ra = reinterpret_cast<const int4*>(row)[i * 2];
        int4 rb = reinterpret_cast<const int4*>(row)[i * 2 + 1];
        int4 ca = reinterpret_cast<const int4*>(col)[i * 2];
        int4 cb = reinterpret_cast<const int4*>(col)[i * 2 + 1];
        g_csrsrc[atomicAdd(&g_cursor[ca.x], 1)] = ra.x;
        g_csrsrc[atomicAdd(&g_cursor[ca.y], 1)] = ra.y;
        g_csrsrc[atomicAdd(&g_cursor[ca.z], 1)] = ra.z;
        g_csrsrc[atomicAdd(&g_cursor[ca.w], 1)] = ra.w;
        g_csrsrc[atomicAdd(&g_cursor[cb.x], 1)] = rb.x;
        g_csrsrc[atomicAdd(&g_cursor[cb.y], 1)] = rb.y;
        g_csrsrc[atomicAdd(&g_cursor[cb.z], 1)] = rb.z;
        g_csrsrc[atomicAdd(&g_cursor[cb.w], 1)] = rb.w;
    }
}

// fp32-path accumulate: 8 half cols from a uint4 into a0..a7
#define ACC8(q)                                                              \
    { float2 f;                                                              \
      f = __half22float2(H2C((q).x)); a0 += f.x; a1 += f.y;                  \
      f = __half22float2(H2C((q).y)); a2 += f.x; a3 += f.y;                  \
      f = __half22float2(H2C((q).z)); a4 += f.x; a5 += f.y;                  \
      f = __half22float2(H2C((q).w)); a6 += f.x; a7 += f.y; }

// fp16 tree (q0+q1)+(q2+q3) then flush to fp32 accumulators a0..a7
#define ACCTREE4(q0, q1, q2, q3)                                             \
    { __half2 t0 = __hadd2(H2C((q0).x), H2C((q1).x));                        \
      __half2 t1 = __hadd2(H2C((q0).y), H2C((q1).y));                        \
      __half2 t2 = __hadd2(H2C((q0).z), H2C((q1).z));                        \
      __half2 t3 = __hadd2(H2C((q0).w), H2C((q1).w));                        \
      __half2 u0 = __hadd2(H2C((q2).x), H2C((q3).x));                        \
      __half2 u1 = __hadd2(H2C((q2).y), H2C((q3).y));                        \
      __half2 u2 = __hadd2(H2C((q2).z), H2C((q3).z));                        \
      __half2 u3 = __hadd2(H2C((q2).w), H2C((q3).w));                        \
      __half2 v0 = __hadd2(t0, u0);                                          \
      __half2 v1 = __hadd2(t1, u1);                                          \
      __half2 v2 = __hadd2(t2, u2);                                          \
      __half2 v3 = __hadd2(t3, u3);                                          \
      float2 f;                                                              \
      f = __half22float2(v0); a0 += f.x; a1 += f.y;                          \
      f = __half22float2(v1); a2 += f.x; a3 += f.y;                          \
      f = __half22float2(v2); a4 += f.x; a5 += f.y;                          \
      f = __half22float2(v3); a6 += f.x; a7 += f.y; }

// ------------------- fused layer 0: fp16-accum interleaved gather + MMA GEMM -------------------

__global__ void __launch_bounds__(512) k_layer0(const float* __restrict__ W0,
                                                const float* __restrict__ b0,
                                                __half2* __restrict__ uout) {
    __shared__ __half sW0[16][72];   // W0 fp16, k rows 9..15 zeroed
    __shared__ __half sA0[64][24];   // agg tile fp16 [node][k], stride 24 halves
    __shared__ float  sB[DD];
    __shared__ float  sDI[64];
    int tid = threadIdx.x;
    int nodeBase = blockIdx.x * 64;
    for (int i = tid; i < 16 * DD; i += 512) {
        int k = i >> 6, c = i & 63;
        sW0[k][c] = __float2half(k < DIN ? W0[k * DD + c] : 0.f);
    }
    if (tid < DD) sB[tid] = b0[tid];
    int unit = tid >> 4;     // 0..31, handles nodes 2*unit, 2*unit+1
    int sl = tid & 15;
    int g = sl >> 1;         // neighbor slot 0..7
    int c2 = sl & 1;         // which uint4 of the 32B row
    const uint4* xs4 = (const uint4*)g_xs16;

    int locA = unit * 2, locB = unit * 2 + 1;
    int nodeA = nodeBase + locA, nodeB = nodeBase + locB;
    __half2 hA2[4], hB2[4];
#pragma unroll
    for (int j = 0; j < 4; j++) { hA2[j] = __floats2half2_rn(0.f, 0.f); hB2[j] = hA2[j]; }
    float diA = 0.f, diB = 0.f;
    int eA = 0, eA1 = 0, eB = 0, eB1 = 0;
    if (nodeA < NN) { diA = g_dinv[nodeA]; eA = g_rowptr[nodeA]; eA1 = g_rowptr[nodeA + 1]; }
    if (nodeB < NN) { diB = g_dinv[nodeB]; eB = g_rowptr[nodeB]; eB1 = g_rowptr[nodeB + 1]; }
    eA += g; eB += g;
    while (eA < eA1 || eB < eB1) {
        if (eA < eA1) {
            uint4 q = xs4[g_csrsrc[eA] * 2 + c2];
            hA2[0] = __hadd2(hA2[0], H2C(q.x));
            hA2[1] = __hadd2(hA2[1], H2C(q.y));
            hA2[2] = __hadd2(hA2[2], H2C(q.z));
            hA2[3] = __hadd2(hA2[3], H2C(q.w));
        }
        if (eB < eB1) {
            uint4 q = xs4[g_csrsrc[eB] * 2 + c2];
            hB2[0] = __hadd2(hB2[0], H2C(q.x));
            hB2[1] = __hadd2(hB2[1], H2C(q.y));
            hB2[2] = __hadd2(hB2[2], H2C(q.z));
            hB2[3] = __hadd2(hB2[3], H2C(q.w));
        }
        eA += 8; eB += 8;
    }
    // flush to fp32
    float accA[8], accB[8];
#pragma unroll
    for (int j = 0; j < 4; j++) {
        float2 fa = __half22float2(hA2[j]);
        float2 fb = __half22float2(hB2[j]);
        accA[2 * j] = fa.x; accA[2 * j + 1] = fa.y;
        accB[2 * j] = fb.x; accB[2 * j + 1] = fb.y;
    }
    // merge 8 neighbor slots within the 16-lane unit (fp32)
#pragma unroll
    for (int o = 8; o >= 2; o >>= 1) {
#pragma unroll
        for (int j = 0; j < 8; j++) {
            accA[j] += __shfl_down_sync(~0u, accA[j], o, 16);
            accB[j] += __shfl_down_sync(~0u, accB[j], o, 16);
        }
    }
    if (sl < 2) {  // sl == c2 for surviving lanes
        if (nodeA < NN) {
            uint4 qs = xs4[nodeA * 2 + sl];
            float2 f;
            f = __half22float2(H2C(qs.x)); accA[0] = diA * (accA[0] + f.x); accA[1] = diA * (accA[1] + f.y);
            f = __half22float2(H2C(qs.y)); accA[2] = diA * (accA[2] + f.x); accA[3] = diA * (accA[3] + f.y);
            f = __half22float2(H2C(qs.z)); accA[4] = diA * (accA[4] + f.x); accA[5] = diA * (accA[5] + f.y);
            f = __half22float2(H2C(qs.w)); accA[6] = diA * (accA[6] + f.x); accA[7] = diA * (accA[7] + f.y);
        } else {
#pragma unroll
            for (int j = 0; j < 8; j++) accA[j] = 0.f;
        }
        if (nodeB < NN) {
            uint4 qs = xs4[nodeB * 2 + sl];
            float2 f;
            f = __half22float2(H2C(qs.x)); accB[0] = diB * (accB[0] + f.x); accB[1] = diB * (accB[1] + f.y);
            f = __half22float2(H2C(qs.y)); accB[2] = diB * (accB[2] + f.x); accB[3] = diB * (accB[3] + f.y);
            f = __half22float2(H2C(qs.z)); accB[4] = diB * (accB[4] + f.x); accB[5] = diB * (accB[5] + f.y);
            f = __half22float2(H2C(qs.w)); accB[6] = diB * (accB[6] + f.x); accB[7] = diB * (accB[7] + f.y);
        } else {
#pragma unroll
            for (int j = 0; j < 8; j++) accB[j] = 0.f;
        }
        // pack fp16 and store to sA0[node][k]
        __half2 p0 = __floats2half2_rn(accA[0], accA[1]);
        __half2 p1 = __floats2half2_rn(accA[2], accA[3]);
        __half2 p2 = __floats2half2_rn(accA[4], accA[5]);
        __half2 p3 = __floats2half2_rn(accA[6], accA[7]);
        uint4 q;
        q.x = *reinterpret_cast<unsigned int*>(&p0);
        q.y = *reinterpret_cast<unsigned int*>(&p1);
        q.z = *reinterpret_cast<unsigned int*>(&p2);
        q.w = *reinterpret_cast<unsigned int*>(&p3);
        *reinterpret_cast<uint4*>(&sA0[locA][sl * 8]) = q;
        p0 = __floats2half2_rn(accB[0], accB[1]);
        p1 = __floats2half2_rn(accB[2], accB[3]);
        p2 = __floats2half2_rn(accB[4], accB[5]);
        p3 = __floats2half2_rn(accB[6], accB[7]);
        q.x = *reinterpret_cast<unsigned int*>(&p0);
        q.y = *reinterpret_cast<unsigned int*>(&p1);
        q.z = *reinterpret_cast<unsigned int*>(&p2);
        q.w = *reinterpret_cast<unsigned int*>(&p3);
        *reinterpret_cast<uint4*>(&sA0[locB][sl * 8]) = q;
        if (sl == 0) { sDI[locA] = diA; sDI[locB] = diB; }
    }
    __syncthreads();
    // MMA: warp (mi,ni) computes nodes 16mi..16mi+15 x cols 16ni..16ni+15, K=16
    int lane = tid & 31;
    int wid = tid >> 5;
    int mi = wid >> 2, ni = wid & 3;
    float c0[4] = {0.f, 0.f, 0.f, 0.f};
    float c1[4] = {0.f, 0.f, 0.f, 0.f};
    unsigned int aBase = smem_u32(&sA0[16 * mi + (lane & 15)][(lane >> 4) * 8]);
    unsigned int bBase = smem_u32(&sW0[lane & 15][16 * ni + ((lane >> 4) << 3)]);
    {
        unsigned int a0, a1, a2, a3, b0, b1, b2, b3;
        ldmx4(a0, a1, a2, a3, aBase);
        ldmx4t(b0, b1, b2, b3, bBase);
        mma16816(c0, a0, a1, a2, a3, b0, b1);
        mma16816(c1, a0, a1, a2, a3, b2, b3);
    }
    int r0 = 16 * mi + (lane >> 2);
    int cb0 = 16 * ni + (lane & 3) * 2;
#pragma unroll
    for (int t2 = 0; t2 < 2; t2++) {
        const float* cc = t2 ? c1 : c0;
        int cb = cb0 + t2 * 8;
        float bx = sB[cb], by = sB[cb + 1];
#pragma unroll
        for (int rh = 0; rh < 2; rh++) {
            int r = r0 + rh * 8;
            int n = nodeBase + r;
            if (n < NN) {
                float sc = sDI[r];
                float v0 = cc[2 * rh] + bx;
                float v1 = cc[2 * rh + 1] + by;
                uout[n * 32 + (cb >> 1)] =
                    __floats2half2_rn(sc * tanh_a(v0), sc * tanh_a(v1));
            }
        }
    }
}

// ------------------- fused layer: scalar-index fp16-tree gather + fp16 MMA GEMM (R13) -------------------

template <bool OUT_HALF, bool PRESCALE>
__global__ void __launch_bounds__(512) k_layer(const __half2* __restrict__ uin,
                                               const float* __restrict__ W,
                                               const float* __restrict__ bias,
                                               void* __restrict__ uout) {
    __shared__ __half sA[64][72];    // agg tile fp16, stride 72 (ldmatrix conflict-free)
    __shared__ __half sBW[64][72];   // W fp16 [k][col]
    __shared__ float  sB[DD];
    __shared__ float  sDI[64];
    int tid = threadIdx.x;
    int nodeBase = blockIdx.x * 64;
    for (int i = tid; i < DD * DD; i += 512)
        sBW[i >> 6][i & 63] = __float2half(W[i]);
    if (tid < DD) sB[tid] = bias[tid];
    int w = tid >> 5, lid = tid & 31;
    int hw = lid >> 4;      // node of pair
    int sl = lid & 15;
    int g8 = sl >> 3;       // neighbor slot (0/1)
    int c8 = sl & 7;        // uint4 col (half-cols 8c8..8c8+7)
    const uint4* u4 = (const uint4*)uin;
#pragma unroll
    for (int pass = 0; pass < 2; pass++) {
        int local = w * 4 + pass * 2 + hw;
        int node = nodeBase + local;
        float a0 = 0.f, a1 = 0.f, a2 = 0.f, a3 = 0.f;
        float a4 = 0.f, a5 = 0.f, a6 = 0.f, a7 = 0.f;
        float di = 0.f;
        if (node < NN) {
            di = g_dinv[node];
            int e = g_rowptr[node], e1 = g_rowptr[node + 1];
            for (; e + 8 <= e1; e += 8) {
                int s0 = g_csrsrc[e + g8];
                int s1 = g_csrsrc[e + 2 + g8];
                int s2 = g_csrsrc[e + 4 + g8];
                int s3 = g_csrsrc[e + 6 + g8];
                uint4 q0 = u4[s0 * 8 + c8];
                uint4 q1 = u4[s1 * 8 + c8];
                uint4 q2 = u4[s2 * 8 + c8];
                uint4 q3 = u4[s3 * 8 + c8];
                ACCTREE4(q0, q1, q2, q3);
            }
            for (int e2 = e + g8; e2 < e1; e2 += 2) {
                uint4 q = u4[g_csrsrc[e2] * 8 + c8]; ACC8(q);
            }
        }
        a0 += __shfl_down_sync(~0u, a0, 8, 16);
        a1 += __shfl_down_sync(~0u, a1, 8, 16);
        a2 += __shfl_down_sync(~0u, a2, 8, 16);
        a3 += __shfl_down_sync(~0u, a3, 8, 16);
        a4 += __shfl_down_sync(~0u, a4, 8, 16);
        a5 += __shfl_down_sync(~0u, a5, 8, 16);
        a6 += __shfl_down_sync(~0u, a6, 8, 16);
        a7 += __shfl_down_sync(~0u, a7, 8, 16);
        if (sl < 8) {
            if (node < NN) {
                uint4 qs = u4[node * 8 + c8];
                float2 f;
                f = __half22float2(H2C(qs.x)); a0 = di * (a0 + f.x); a1 = di * (a1 + f.y);
                f = __half22float2(H2C(qs.y)); a2 = di * (a2 + f.x); a3 = di * (a3 + f.y);
                f = __half22float2(H2C(qs.z)); a4 = di * (a4 + f.x); a5 = di * (a5 + f.y);
                f = __half22float2(H2C(qs.w)); a6 = di * (a6 + f.x); a7 = di * (a7 + f.y);
            }
            __half2 h0 = __floats2half2_rn(a0, a1);
            __half2 h1 = __floats2half2_rn(a2, a3);
            __half2 h2 = __floats2half2_rn(a4, a5);
            __half2 h3 = __floats2half2_rn(a6, a7);
            uint4 q;
            q.x = *reinterpret_cast<unsigned int*>(&h0);
            q.y = *reinterpret_cast<unsigned int*>(&h1);
            q.z = *reinterpret_cast<unsigned int*>(&h2);
            q.w = *reinterpret_cast<unsigned int*>(&h3);
            *reinterpret_cast<uint4*>(&sA[local][c8 * 8]) = q;
            if (c8 == 0) sDI[local] = di;
        }
    }
    __syncthreads();
    int lane = tid & 31;
    int wid = tid >> 5;
    int mi = wid >> 2, ni = wid & 3;
    float c0[4] = {0.f, 0.f, 0.f, 0.f};
    float c1[4] = {0.f, 0.f, 0.f, 0.f};
    unsigned int aBase = smem_u32(&sA[16 * mi + (lane & 15)][(lane >> 4) * 8]);
    unsigned int bBase = smem_u32(&sBW[lane & 15][16 * ni + ((lane >> 4) << 3)]);
#pragma unroll
    for (int kk = 0; kk < 4; kk++) {
        unsigned int a0, a1, a2, a3, b0, b1, b2, b3;
        ldmx4(a0, a1, a2, a3, aBase + kk * 32);
        ldmx4t(b0, b1, b2, b3, bBase + kk * 16 * 144);
        mma16816(c0, a0, a1, a2, a3, b0, b1);
        mma16816(c1, a0, a1, a2, a3, b2, b3);
    }
    int r0 = 16 * mi + (lane >> 2);
    int cb0 = 16 * ni + (lane & 3) * 2;
#pragma unroll
    for (int t2 = 0; t2 < 2; t2++) {
        const float* cc = t2 ? c1 : c0;
        int cb = cb0 + t2 * 8;
        float bx = sB[cb], by = sB[cb + 1];
#pragma unroll
        for (int rh = 0; rh < 2; rh++) {
            int r = r0 + rh * 8;
            int n = nodeBase + r;
            if (n < NN) {
                float v0 = cc[2 * rh] + bx;
                float v1 = cc[2 * rh + 1] + by;
                if (OUT_HALF) {
                    float sc = PRESCALE ? sDI[r] : 1.0f;
                    ((__half2*)uout)[n * 32 + (cb >> 1)] =
                        __floats2half2_rn(sc * tanh_a(v0), sc * tanh_a(v1));
                } else {
                    ((float2*)uout)[n * 32 + (cb >> 1)] =
                        make_float2(tanh_a(v0), tanh_a(v1));
                }
            }
        }
    }
}

// ------------------- pooling + head -------------------
__global__ void k_pool(const float* __restrict__ h, const float* __restrict__ Wout,
                       const float* __restrict__ bout, float* __restrict__ out) {
    int g = (blockIdx.x * blockDim.x + threadIdx.x) >> 5;
    int lid = threadIdx.x & 31;
    if (g >= GG) return;
    long long gs = (long long)g * NN;
    int start = (int)((gs + GG - 1) / GG);
    int end = (int)((gs + NN + GG - 1) / GG);
    if (end > NN) end = NN;
    const float2* h2 = (const float2*)h;
    float2 mx = make_float2(-INFINITY, -INFINITY);
    float2 sm = make_float2(0.f, 0.f);
    for (int i = start; i < end; i++) {
        float2 v = h2[i * 32 + lid];
        mx.x = fmaxf(mx.x, v.x);
        mx.y = fmaxf(mx.y, v.y);
        sm.x += v.x;
        sm.y += v.y;
    }
    int cnt = end - start; if (cnt < 1) cnt = 1;
    float inv = 1.0f / (float)cnt;
    const float2* w2 = (const float2*)Wout;
    float2 wmx = w2[lid];
    float2 wmn = w2[32 + lid];
    float v = mx.x * wmx.x + mx.y * wmx.y
            + (sm.x * inv) * wmn.x + (sm.y * inv) * wmn.y;
#pragma unroll
    for (int o = 16; o; o >>= 1) v += __shfl_down_sync(0xffffffffu, v, o);
    if (lid == 0) out[g] = v + bout[0];
}

// ------------------- launch -------------------

extern "C" void kernel_launch(void* const* d_in, const int* in_sizes, int n_in,
                              void* d_out, int out_size) {
    const float* x    = (const float*)d_in[0];
    const int*   ei   = (const int*)d_in[1];
    const float* W0   = (const float*)d_in[3];
    const float* b0   = (const float*)d_in[4];
    const float* W1   = (const float*)d_in[5];
    const float* b1   = (const float*)d_in[6];
    const float* W2   = (const float*)d_in[7];
    const float* b2   = (const float*)d_in[8];
    const float* W3   = (const float*)d_in[9];
    const float* b3   = (const float*)d_in[10];
    const float* Wout = (const float*)d_in[11];
    const float* bout = (const float*)d_in[12];
    float* out = (float*)d_out;

    const int* erow = ei;        // sources
    const int* ecol = ei + EE;   // destinations

    float *hA, *hB;
    cudaGetSymbolAddress((void**)&hA, g_hA);
    cudaGetSymbolAddress((void**)&hB, g_hB);

    int eB8 = (EE / 8 + 255) / 256;   // 391: 8 edges/thread
    int gB = (NN + 63) / 64;          // 782
    int pB = (GG * 32 + 255) / 256;

    k_hist<<<eB8, 256>>>(ecol);
    k_scan<<<NBLK, 256>>>(x);
    k_fill<<<eB8, 256>>>(erow, ecol);

    k_layer0<<<gB, 512>>>(W0, b0, (__half2*)hA);
    k_layer<true, true><<<gB, 512>>>((const __half2*)hA, W1, b1, hB);
    k_layer<true, true><<<gB, 512>>>((const __half2*)hB, W2, b2, hA);
    k_layer<false, false><<<gB, 512>>>((const __half2*)hA, W3, b3, hB);

    k_pool<<<pB, 256>>>(hB, Wout, bout, out);
}

// round 17
// speedup vs baseline: 1.3243x; 1.0429x over previous
#include <cuda_runtime.h>
#include <cuda_fp16.h>
#include <math.h>

#define NN 50000
#define EE 800000
#define GG 1024
#define DD 64
#define DIN 9
#define NBLK ((NN + 255) / 256)    // 196

// ---- scratch ----
__device__ int   g_deg[NN];        // all-zero at entry; re-zeroed in k_fill each call
__device__ float g_dinv[NN];
__device__ int   g_rowptr[NN + 1];
__device__ int   g_cursor[NN];
__device__ int   g_csrsrc[EE];
__device__ unsigned long long g_blkDesc[NBLK];  // zeroed in k_hist each call
__device__ uint4 g_xs16[NN * 2];   // fp16 input features, 16 halves/node (9 used)
__device__ float g_hA[NN * DD];
__device__ float g_hB[NN * DD];
__device__ __half g_W016[16 * 72];      // W0 fp16, [k][c] stride 72, rows 9..15 zero
__device__ __half g_W16[3][64 * 72];    // W1..W3 fp16, [k][c] stride 72

__device__ __forceinline__ float tanh_a(float x) {
    float y;
    asm("tanh.approx.f32 %0, %1;" : "=f"(y) : "f"(x));
    return y;
}
__device__ __forceinline__ unsigned int smem_u32(const void* p) {
    return (unsigned int)__cvta_generic_to_shared(p);
}
__device__ __forceinline__ void ldmx4(unsigned int& r0, unsigned int& r1,
                                      unsigned int& r2, unsigned int& r3, unsigned int a) {
    asm volatile("ldmatrix.sync.aligned.m8n8.x4.shared.b16 {%0,%1,%2,%3}, [%4];"
                 : "=r"(r0), "=r"(r1), "=r"(r2), "=r"(r3) : "r"(a));
}
__device__ __forceinline__ void ldmx4t(unsigned int& r0, unsigned int& r1,
                                       unsigned int& r2, unsigned int& r3, unsigned int a) {
    asm volatile("ldmatrix.sync.aligned.m8n8.x4.trans.shared.b16 {%0,%1,%2,%3}, [%4];"
                 : "=r"(r0), "=r"(r1), "=r"(r2), "=r"(r3) : "r"(a));
}
__device__ __forceinline__ void mma16816(float* c, unsigned int a0, unsigned int a1,
                                         unsigned int a2, unsigned int a3,
                                         unsigned int b0, unsigned int b1) {
    asm volatile("mma.sync.aligned.m16n8k16.row.col.f32.f16.f16.f32 "
                 "{%0,%1,%2,%3}, {%4,%5,%6,%7}, {%8,%9}, {%0,%1,%2,%3};"
                 : "+f"(c[0]), "+f"(c[1]), "+f"(c[2]), "+f"(c[3])
                 : "r"(a0), "r"(a1), "r"(a2), "r"(a3), "r"(b0), "r"(b1));
}

#define H2C(p) (*(const __half2*)&(p))

// ------------------- preprocessing -------------------

// histogram (8 edges/thread) + zero scan descriptors + pre-convert weights to fp16
__global__ void k_hist(const int* __restrict__ col,
                       const float* __restrict__ W0, const float* __restrict__ W1,
                       const float* __restrict__ W2, const float* __restrict__ W3) {
    int i = blockIdx.x * blockDim.x + threadIdx.x;
    if (i < NBLK) g_blkDesc[i] = 0ULL;
    // W1..W3 conversion: 3 x 4096 elements
    if (i < 3 * 4096) {
        int l = i >> 12, r = i & 4095;
        int k = r >> 6, c = r & 63;
        const float* W = (l == 0) ? W1 : (l == 1) ? W2 : W3;
        g_W16[l][k * 72 + c] = __float2half(W[r]);
    }
    // W0 conversion: 16 x 64 (rows 9..15 zero)
    int j = i - 3 * 4096;
    if (j >= 0 && j < 16 * 64) {
        int k = j >> 6, c = j & 63;
        g_W016[k * 72 + c] = __float2half(k < DIN ? W0[k * DD + c] : 0.f);
    }
    long long base = (long long)i * 8;
    if (base < EE) {
        int4 a = reinterpret_cast<const int4*>(col)[i * 2];
        int4 b = reinterpret_cast<const int4*>(col)[i * 2 + 1];
        atomicAdd(&g_deg[a.x], 1); atomicAdd(&g_deg[a.y], 1);
        atomicAdd(&g_deg[a.z], 1); atomicAdd(&g_deg[a.w], 1);
        atomicAdd(&g_deg[b.x], 1); atomicAdd(&g_deg[b.y], 1);
        atomicAdd(&g_deg[b.z], 1); atomicAdd(&g_deg[b.w], 1);
    }
}

__global__ void k_scan(const float* __restrict__ x) {
    __shared__ int wsum[8];
    __shared__ int sprefix;
    int b = blockIdx.x, t = threadIdx.x;
    int i = b * 256 + t;
    int lane = t & 31, w = t >> 5;
    int v = (i < NN) ? g_deg[i] : 0;
    int s = v;
#pragma unroll
    for (int o = 1; o < 32; o <<= 1) {
        int u = __shfl_up_sync(~0u, s, o);
        if (lane >= o) s += u;
    }
    if (lane == 31) wsum[w] = s;
    __syncthreads();
    if (w == 0) {
        int ws = (lane < 8) ? wsum[lane] : 0;
#pragma unroll
        for (int o = 1; o < 8; o <<= 1) {
            int u = __shfl_up_sync(0xffu, ws, o);
            if (lane >= o) ws += u;
        }
        if (lane < 8) wsum[lane] = ws;
    }
    __syncthreads();
    int total = wsum[7];
    if (t == 0) {
        if (b == 0) {
            atomicExch(&g_blkDesc[0], ((unsigned long long)total << 2) | 2ULL);
            sprefix = 0;
        } else {
            atomicExch(&g_blkDesc[b], ((unsigned long long)total << 2) | 1ULL);
            int run = 0;
            for (int j = b - 1; j >= 0; j--) {
                unsigned long long d;
                do { d = *((volatile unsigned long long*)&g_blkDesc[j]); } while ((d & 3ULL) == 0ULL);
                run += (int)(d >> 2);
                if ((d & 3ULL) == 2ULL) break;
            }
            sprefix = run;
            atomicExch(&g_blkDesc[b], ((unsigned long long)(total + run) << 2) | 2ULL);
        }
    }
    __syncthreads();
    int excl = sprefix + (w > 0 ? wsum[w - 1] : 0) + (s - v);
    if (i < NN) {
        g_rowptr[i] = excl;
        g_cursor[i] = excl;
        float di = rsqrtf((float)v + 1.0f);  // +1 self loop
        g_dinv[i] = di;
        __half2* xo = (__half2*)g_xs16;
        float f[10];
#pragma unroll
        for (int c = 0; c < DIN; c++) f[c] = di * x[i * DIN + c];
        f[9] = 0.f;
#pragma unroll
        for (int j = 0; j < 5; j++)
            xo[i * 8 + j] = __floats2half2_rn(f[2 * j], f[2 * j + 1]);
#pragma unroll
        for (int j = 5; j < 8; j++)
            xo[i * 8 + j] = __floats2half2_rn(0.f, 0.f);
    }
    if (i == 0) g_rowptr[NN] = EE;
}

__global__ void k_fill(const int* __restrict__ row, const int* __restrict__ col) {
    int i = blockIdx.x * blockDim.x + threadIdx.x;
    if (i < NN) g_deg[i] = 0;
    long long base = (long long)i * 8;
    if (base < EE) {
        int4 ra = reinterpret_cast<const int4*>(row)[i * 2];
        int4 rb = reinterpret_cast<const int4*>(row)[i * 2 + 1];
        int4 ca = reinterpret_cast<const int4*>(col)[i * 2];
        int4 cb = reinterpret_cast<const int4*>(col)[i * 2 + 1];
        g_csrsrc[atomicAdd(&g_cursor[ca.x], 1)] = ra.x;
        g_csrsrc[atomicAdd(&g_cursor[ca.y], 1)] = ra.y;
        g_csrsrc[atomicAdd(&g_cursor[ca.z], 1)] = ra.z;
        g_csrsrc[atomicAdd(&g_cursor[ca.w], 1)] = ra.w;
        g_csrsrc[atomicAdd(&g_cursor[cb.x], 1)] = rb.x;
        g_csrsrc[atomicAdd(&g_cursor[cb.y], 1)] = rb.y;
        g_csrsrc[atomicAdd(&g_cursor[cb.z], 1)] = rb.z;
        g_csrsrc[atomicAdd(&g_cursor[cb.w], 1)] = rb.w;
    }
}

// fp32-path accumulate: 8 half cols from a uint4 into a0..a7
#define ACC8(q)                                                              \
    { float2 f;                                                              \
      f = __half22float2(H2C((q).x)); a0 += f.x; a1 += f.y;                  \
      f = __half22float2(H2C((q).y)); a2 += f.x; a3 += f.y;                  \
      f = __half22float2(H2C((q).z)); a4 += f.x; a5 += f.y;                  \
      f = __half22float2(H2C((q).w)); a6 += f.x; a7 += f.y; }

// fp16 tree (q0+q1)+(q2+q3) then flush to fp32 accumulators a0..a7
#define ACCTREE4(q0, q1, q2, q3)                                             \
    { __half2 t0 = __hadd2(H2C((q0).x), H2C((q1).x));                        \
      __half2 t1 = __hadd2(H2C((q0).y), H2C((q1).y));                        \
      __half2 t2 = __hadd2(H2C((q0).z), H2C((q1).z));                        \
      __half2 t3 = __hadd2(H2C((q0).w), H2C((q1).w));                        \
      __half2 u0 = __hadd2(H2C((q2).x), H2C((q3).x));                        \
      __half2 u1 = __hadd2(H2C((q2).y), H2C((q3).y));                        \
      __half2 u2 = __hadd2(H2C((q2).z), H2C((q3).z));                        \
      __half2 u3 = __hadd2(H2C((q2).w), H2C((q3).w));                        \
      __half2 v0 = __hadd2(t0, u0);                                          \
      __half2 v1 = __hadd2(t1, u1);                                          \
      __half2 v2 = __hadd2(t2, u2);                                          \
      __half2 v3 = __hadd2(t3, u3);                                          \
      float2 f;                                                              \
      f = __half22float2(v0); a0 += f.x; a1 += f.y;                          \
      f = __half22float2(v1); a2 += f.x; a3 += f.y;                          \
      f = __half22float2(v2); a4 += f.x; a5 += f.y;                          \
      f = __half22float2(v3); a6 += f.x; a7 += f.y; }

// ------------------- fused layer 0: fp16-accum interleaved gather + MMA GEMM -------------------

__global__ void __launch_bounds__(512, 4) k_layer0(const float* __restrict__ b0,
                                                   __half2* __restrict__ uout) {
    __shared__ __half sW0[16][72];   // W0 fp16 (pre-converted)
    __shared__ __half sA0[64][24];   // agg tile fp16 [node][k], stride 24 halves
    __shared__ float  sB[DD];
    __shared__ float  sDI[64];
    int tid = threadIdx.x;
    int nodeBase = blockIdx.x * 64;
    // copy pre-converted W0: 16*72 halves = 144 uint4
    if (tid < 144)
        reinterpret_cast<uint4*>(&sW0[0][0])[tid] =
            reinterpret_cast<const uint4*>(g_W016)[tid];
    if (tid < DD) sB[tid] = b0[tid];
    int unit = tid >> 4;     // 0..31, handles nodes 2*unit, 2*unit+1
    int sl = tid & 15;
    int g = sl >> 1;         // neighbor slot 0..7
    int c2 = sl & 1;         // which uint4 of the 32B row
    const uint4* xs4 = (const uint4*)g_xs16;

    int locA = unit * 2, locB = unit * 2 + 1;
    int nodeA = nodeBase + locA, nodeB = nodeBase + locB;
    __half2 hA2[4], hB2[4];
#pragma unroll
    for (int j = 0; j < 4; j++) { hA2[j] = __floats2half2_rn(0.f, 0.f); hB2[j] = hA2[j]; }
    float diA = 0.f, diB = 0.f;
    int eA = 0, eA1 = 0, eB = 0, eB1 = 0;
    if (nodeA < NN) { diA = g_dinv[nodeA]; eA = g_rowptr[nodeA]; eA1 = g_rowptr[nodeA + 1]; }
    if (nodeB < NN) { diB = g_dinv[nodeB]; eB = g_rowptr[nodeB]; eB1 = g_rowptr[nodeB + 1]; }
    eA += g; eB += g;
    while (eA < eA1 || eB < eB1) {
        if (eA < eA1) {
            uint4 q = xs4[g_csrsrc[eA] * 2 + c2];
            hA2[0] = __hadd2(hA2[0], H2C(q.x));
            hA2[1] = __hadd2(hA2[1], H2C(q.y));
            hA2[2] = __hadd2(hA2[2], H2C(q.z));
            hA2[3] = __hadd2(hA2[3], H2C(q.w));
        }
        if (eB < eB1) {
            uint4 q = xs4[g_csrsrc[eB] * 2 + c2];
            hB2[0] = __hadd2(hB2[0], H2C(q.x));
            hB2[1] = __hadd2(hB2[1], H2C(q.y));
            hB2[2] = __hadd2(hB2[2], H2C(q.z));
            hB2[3] = __hadd2(hB2[3], H2C(q.w));
        }
        eA += 8; eB += 8;
    }
    // flush to fp32
    float accA[8], accB[8];
#pragma unroll
    for (int j = 0; j < 4; j++) {
        float2 fa = __half22float2(hA2[j]);
        float2 fb = __half22float2(hB2[j]);
        accA[2 * j] = fa.x; accA[2 * j + 1] = fa.y;
        accB[2 * j] = fb.x; accB[2 * j + 1] = fb.y;
    }
    // merge 8 neighbor slots within the 16-lane unit (fp32)
#pragma unroll
    for (int o = 8; o >= 2; o >>= 1) {
#pragma unroll
        for (int j = 0; j < 8; j++) {
            accA[j] += __shfl_down_sync(~0u, accA[j], o, 16);
            accB[j] += __shfl_down_sync(~0u, accB[j], o, 16);
        }
    }
    if (sl < 2) {  // sl == c2 for surviving lanes
        if (nodeA < NN) {
            uint4 qs = xs4[nodeA * 2 + sl];
            float2 f;
            f = __half22float2(H2C(qs.x)); accA[0] = diA * (accA[0] + f.x); accA[1] = diA * (accA[1] + f.y);
            f = __half22float2(H2C(qs.y)); accA[2] = diA * (accA[2] + f.x); accA[3] = diA * (accA[3] + f.y);
            f = __half22float2(H2C(qs.z)); accA[4] = diA * (accA[4] + f.x); accA[5] = diA * (accA[5] + f.y);
            f = __half22float2(H2C(qs.w)); accA[6] = diA * (accA[6] + f.x); accA[7] = diA * (accA[7] + f.y);
        } else {
#pragma unroll
            for (int j = 0; j < 8; j++) accA[j] = 0.f;
        }
        if (nodeB < NN) {
            uint4 qs = xs4[nodeB * 2 + sl];
            float2 f;
            f = __half22float2(H2C(qs.x)); accB[0] = diB * (accB[0] + f.x); accB[1] = diB * (accB[1] + f.y);
            f = __half22float2(H2C(qs.y)); accB[2] = diB * (accB[2] + f.x); accB[3] = diB * (accB[3] + f.y);
            f = __half22float2(H2C(qs.z)); accB[4] = diB * (accB[4] + f.x); accB[5] = diB * (accB[5] + f.y);
            f = __half22float2(H2C(qs.w)); accB[6] = diB * (accB[6] + f.x); accB[7] = diB * (accB[7] + f.y);
        } else {
#pragma unroll
            for (int j = 0; j < 8; j++) accB[j] = 0.f;
        }
        __half2 p0 = __floats2half2_rn(accA[0], accA[1]);
        __half2 p1 = __floats2half2_rn(accA[2], accA[3]);
        __half2 p2 = __floats2half2_rn(accA[4], accA[5]);
        __half2 p3 = __floats2half2_rn(accA[6], accA[7]);
        uint4 q;
        q.x = *reinterpret_cast<unsigned int*>(&p0);
        q.y = *reinterpret_cast<unsigned int*>(&p1);
        q.z = *reinterpret_cast<unsigned int*>(&p2);
        q.w = *reinterpret_cast<unsigned int*>(&p3);
        *reinterpret_cast<uint4*>(&sA0[locA][sl * 8]) = q;
        p0 = __floats2half2_rn(accB[0], accB[1]);
        p1 = __floats2half2_rn(accB[2], accB[3]);
        p2 = __floats2half2_rn(accB[4], accB[5]);
        p3 = __floats2half2_rn(accB[6], accB[7]);
        q.x = *reinterpret_cast<unsigned int*>(&p0);
        q.y = *reinterpret_cast<unsigned int*>(&p1);
        q.z = *reinterpret_cast<unsigned int*>(&p2);
        q.w = *reinterpret_cast<unsigned int*>(&p3);
        *reinterpret_cast<uint4*>(&sA0[locB][sl * 8]) = q;
        if (sl == 0) { sDI[locA] = diA; sDI[locB] = diB; }
    }
    __syncthreads();
    // MMA: warp (mi,ni) computes nodes 16mi..16mi+15 x cols 16ni..16ni+15, K=16
    int lane = tid & 31;
    int wid = tid >> 5;
    int mi = wid >> 2, ni = wid & 3;
    float c0[4] = {0.f, 0.f, 0.f, 0.f};
    float c1[4] = {0.f, 0.f, 0.f, 0.f};
    unsigned int aBase = smem_u32(&sA0[16 * mi + (lane & 15)][(lane >> 4) * 8]);
    unsigned int bBase = smem_u32(&sW0[lane & 15][16 * ni + ((lane >> 4) << 3)]);
    {
        unsigned int a0, a1, a2, a3, b0, b1, b2, b3;
        ldmx4(a0, a1, a2, a3, aBase);
        ldmx4t(b0, b1, b2, b3, bBase);
        mma16816(c0, a0, a1, a2, a3, b0, b1);
        mma16816(c1, a0, a1, a2, a3, b2, b3);
    }
    int r0 = 16 * mi + (lane >> 2);
    int cb0 = 16 * ni + (lane & 3) * 2;
#pragma unroll
    for (int t2 = 0; t2 < 2; t2++) {
        const float* cc = t2 ? c1 : c0;
        int cb = cb0 + t2 * 8;
        float bx = sB[cb], by = sB[cb + 1];
#pragma unroll
        for (int rh = 0; rh < 2; rh++) {
            int r = r0 + rh * 8;
            int n = nodeBase + r;
            if (n < NN) {
                float sc = sDI[r];
                float v0 = cc[2 * rh] + bx;
                float v1 = cc[2 * rh + 1] + by;
                uout[n * 32 + (cb >> 1)] =
                    __floats2half2_rn(sc * tanh_a(v0), sc * tanh_a(v1));
            }
        }
    }
}

// ------------------- fused layer: scalar-index fp16-tree gather + fp16 MMA GEMM -------------------

template <bool OUT_HALF, bool PRESCALE>
__global__ void __launch_bounds__(512) k_layer(const __half2* __restrict__ uin,
                                               const __half* __restrict__ Wh,
                                               const float* __restrict__ bias,
                                               void* __restrict__ uout) {
    __shared__ __half sA[64][72];    // agg tile fp16, stride 72 (ldmatrix conflict-free)
    __shared__ __half sBW[64][72];   // W fp16 [k][col] (pre-converted)
    __shared__ float  sB[DD];
    __shared__ float  sDI[64];
    int tid = threadIdx.x;
    int nodeBase = blockIdx.x * 64;
    // copy pre-converted W: 64*72 halves = 576 uint4
    for (int i = tid; i < 576; i += 512)
        reinterpret_cast<uint4*>(&sBW[0][0])[i] = reinterpret_cast<const uint4*>(Wh)[i];
    if (tid < DD) sB[tid] = bias[tid];
    int w = tid >> 5, lid = tid & 31;
    int hw = lid >> 4;      // node of pair
    int sl = lid & 15;
    int g8 = sl >> 3;       // neighbor slot (0/1)
    int c8 = sl & 7;        // uint4 col (half-cols 8c8..8c8+7)
    const uint4* u4 = (const uint4*)uin;
#pragma unroll
    for (int pass = 0; pass < 2; pass++) {
        int local = w * 4 + pass * 2 + hw;
        int node = nodeBase + local;
        float a0 = 0.f, a1 = 0.f, a2 = 0.f, a3 = 0.f;
        float a4 = 0.f, a5 = 0.f, a6 = 0.f, a7 = 0.f;
        float di = 0.f;
        if (node < NN) {
            di = g_dinv[node];
            int e = g_rowptr[node], e1 = g_rowptr[node + 1];
            for (; e + 8 <= e1; e += 8) {
                int s0 = g_csrsrc[e + g8];
                int s1 = g_csrsrc[e + 2 + g8];
                int s2 = g_csrsrc[e + 4 + g8];
                int s3 = g_csrsrc[e + 6 + g8];
                uint4 q0 = u4[s0 * 8 + c8];
                uint4 q1 = u4[s1 * 8 + c8];
                uint4 q2 = u4[s2 * 8 + c8];
                uint4 q3 = u4[s3 * 8 + c8];
                ACCTREE4(q0, q1, q2, q3);
            }
            for (int e2 = e + g8; e2 < e1; e2 += 2) {
                uint4 q = u4[g_csrsrc[e2] * 8 + c8]; ACC8(q);
            }
        }
        a0 += __shfl_down_sync(~0u, a0, 8, 16);
        a1 += __shfl_down_sync(~0u, a1, 8, 16);
        a2 += __shfl_down_sync(~0u, a2, 8, 16);
        a3 += __shfl_down_sync(~0u, a3, 8, 16);
        a4 += __shfl_down_sync(~0u, a4, 8, 16);
        a5 += __shfl_down_sync(~0u, a5, 8, 16);
        a6 += __shfl_down_sync(~0u, a6, 8, 16);
        a7 += __shfl_down_sync(~0u, a7, 8, 16);
        if (sl < 8) {
            if (node < NN) {
                uint4 qs = u4[node * 8 + c8];
                float2 f;
                f = __half22float2(H2C(qs.x)); a0 = di * (a0 + f.x); a1 = di * (a1 + f.y);
                f = __half22float2(H2C(qs.y)); a2 = di * (a2 + f.x); a3 = di * (a3 + f.y);
                f = __half22float2(H2C(qs.z)); a4 = di * (a4 + f.x); a5 = di * (a5 + f.y);
                f = __half22float2(H2C(qs.w)); a6 = di * (a6 + f.x); a7 = di * (a7 + f.y);
            }
            __half2 h0 = __floats2half2_rn(a0, a1);
            __half2 h1 = __floats2half2_rn(a2, a3);
            __half2 h2 = __floats2half2_rn(a4, a5);
            __half2 h3 = __floats2half2_rn(a6, a7);
            uint4 q;
            q.x = *reinterpret_cast<unsigned int*>(&h0);
            q.y = *reinterpret_cast<unsigned int*>(&h1);
            q.z = *reinterpret_cast<unsigned int*>(&h2);
            q.w = *reinterpret_cast<unsigned int*>(&h3);
            *reinterpret_cast<uint4*>(&sA[local][c8 * 8]) = q;
            if (c8 == 0) sDI[local] = di;
        }
    }
    __syncthreads();
    int lane = tid & 31;
    int wid = tid >> 5;
    int mi = wid >> 2, ni = wid & 3;
    float c0[4] = {0.f, 0.f, 0.f, 0.f};
    float c1[4] = {0.f, 0.f, 0.f, 0.f};
    unsigned int aBase = smem_u32(&sA[16 * mi + (lane & 15)][(lane >> 4) * 8]);
    unsigned int bBase = smem_u32(&sBW[lane & 15][16 * ni + ((lane >> 4) << 3)]);
#pragma unroll
    for (int kk = 0; kk < 4; kk++) {
        unsigned int a0, a1, a2, a3, b0, b1, b2, b3;
        ldmx4(a0, a1, a2, a3, aBase + kk * 32);
        ldmx4t(b0, b1, b2, b3, bBase + kk * 16 * 144);
        mma16816(c0, a0, a1, a2, a3, b0, b1);
        mma16816(c1, a0, a1, a2, a3, b2, b3);
    }
    int r0 = 16 * mi + (lane >> 2);
    int cb0 = 16 * ni + (lane & 3) * 2;
#pragma unroll
    for (int t2 = 0; t2 < 2; t2++) {
        const float* cc = t2 ? c1 : c0;
        int cb = cb0 + t2 * 8;
        float bx = sB[cb], by = sB[cb + 1];
#pragma unroll
        for (int rh = 0; rh < 2; rh++) {
            int r = r0 + rh * 8;
            int n = nodeBase + r;
            if (n < NN) {
                float v0 = cc[2 * rh] + bx;
                float v1 = cc[2 * rh + 1] + by;
                if (OUT_HALF) {
                    float sc = PRESCALE ? sDI[r] : 1.0f;
                    ((__half2*)uout)[n * 32 + (cb >> 1)] =
                        __floats2half2_rn(sc * tanh_a(v0), sc * tanh_a(v1));
                } else {
                    ((float2*)uout)[n * 32 + (cb >> 1)] =
                        make_float2(tanh_a(v0), tanh_a(v1));
                }
            }
        }
    }
}

// ------------------- pooling + head -------------------
__global__ void k_pool(const float* __restrict__ h, const float* __restrict__ Wout,
                       const float* __restrict__ bout, float* __restrict__ out) {
    int g = (blockIdx.x * blockDim.x + threadIdx.x) >> 5;
    int lid = threadIdx.x & 31;
    if (g >= GG) return;
    long long gs = (long long)g * NN;
    int start = (int)((gs + GG - 1) / GG);
    int end = (int)((gs + NN + GG - 1) / GG);
    if (end > NN) end = NN;
    const float2* h2 = (const float2*)h;
    float2 mx = make_float2(-INFINITY, -INFINITY);
    float2 sm = make_float2(0.f, 0.f);
    for (int i = start; i < end; i++) {
        float2 v = h2[i * 32 + lid];
        mx.x = fmaxf(mx.x, v.x);
        mx.y = fmaxf(mx.y, v.y);
        sm.x += v.x;
        sm.y += v.y;
    }
    int cnt = end - start; if (cnt < 1) cnt = 1;
    float inv = 1.0f / (float)cnt;
    const float2* w2 = (const float2*)Wout;
    float2 wmx = w2[lid];
    float2 wmn = w2[32 + lid];
    float v = mx.x * wmx.x + mx.y * wmx.y
            + (sm.x * inv) * wmn.x + (sm.y * inv) * wmn.y;
#pragma unroll
    for (int o = 16; o; o >>= 1) v += __shfl_down_sync(0xffffffffu, v, o);
    if (lid == 0) out[g] = v + bout[0];
}

// ------------------- launch -------------------

extern "C" void kernel_launch(void* const* d_in, const int* in_sizes, int n_in,
                              void* d_out, int out_size) {
    const float* x    = (const float*)d_in[0];
    const int*   ei   = (const int*)d_in[1];
    const float* W0   = (const float*)d_in[3];
    const float* b0   = (const float*)d_in[4];
    const float* W1   = (const float*)d_in[5];
    const float* b1   = (const float*)d_in[6];
    const float* W2   = (const float*)d_in[7];
    const float* b2   = (const float*)d_in[8];
    const float* W3   = (const float*)d_in[9];
    const float* b3   = (const float*)d_in[10];
    const float* Wout = (const float*)d_in[11];
    const float* bout = (const float*)d_in[12];
    float* out = (float*)d_out;

    const int* erow = ei;        // sources
    const int* ecol = ei + EE;   // destinations

    float *hA, *hB;
    cudaGetSymbolAddress((void**)&hA, g_hA);
    cudaGetSymbolAddress((void**)&hB, g_hB);
    __half* W16;
    cudaGetSymbolAddress((void**)&W16, g_W16);

    int eB8 = (EE / 8 + 255) / 256;   // 391: 8 edges/thread
    int gB = (NN + 63) / 64;          // 782
    int pB = (GG * 32 + 255) / 256;

    k_hist<<<eB8, 256>>>(ecol, W0, W1, W2, W3);
    k_scan<<<NBLK, 256>>>(x);
    k_fill<<<eB8, 256>>>(erow, ecol);

    k_layer0<<<gB, 512>>>(b0, (__half2*)hA);
    k_layer<true, true><<<gB, 512>>>((const __half2*)hA, W16 + 0 * 4608, b1, hB);
    k_layer<true, true><<<gB, 512>>>((const __half2*)hB, W16 + 1 * 4608, b2, hA);
    k_layer<false, false><<<gB, 512>>>((const __half2*)hA, W16 + 2 * 4608, b3, hB);

    k_pool<<<pB, 256>>>(hB, Wout, bout, out);
}